// round 6
// baseline (speedup 1.0000x reference)
#include <cuda_runtime.h>
#include <math.h>

#define H 128
#define DS 64
#define TCH 128
#define MAXN 20000
#define MAXE 640000
#define MAXNC 157

typedef unsigned long long ull;

// ---------------- scratch ----------------
__device__ float g_mi[MAXN * H];
__device__ float g_agg[MAXN * H];
__device__ float g_h1[MAXN * H];
__device__ float g_x[MAXN * H];
__device__ float g_z[MAXN * H];
__device__ float g_xs[MAXN * H];
__device__ float g_delta[MAXN * H];
__device__ float g_Bm[MAXN * DS];
__device__ float g_Cm[MAXN * DS];
__device__ float g_y[MAXN * H];
__device__ float g_P[MAXN * H];
__device__ float g_Q[MAXN * H];
__device__ float g_M[H * H];
__device__ float g_aprod[MAXNC * H * DS];
__device__ float g_bstate[MAXNC * H * DS];
__device__ float g_sstart[MAXNC * H * DS];
__device__ int   g_is64;
// edge materialization + CSR
__device__ float g_mij[MAXE * H];
__device__ float g_eij[MAXE];
__device__ int g_cnt_r[MAXN], g_cnt_c[MAXN], g_cur_r[MAXN], g_cur_c[MAXN];
__device__ int g_off_r[MAXN + 1], g_off_c[MAXN + 1];
__device__ int g_eid_r[MAXE], g_eid_c[MAXE];

// ---------------- helpers ----------------
__device__ __forceinline__ float sigm(float v) { return 1.f / (1.f + __expf(-v)); }
__device__ __forceinline__ float silu(float v) { return v / (1.f + __expf(-v)); }
__device__ __forceinline__ float softplus(float v) { return (v > 20.f) ? v : log1pf(__expf(v)); }

__device__ __forceinline__ ull pk2(float a, float b) {
    ull r; asm("mov.b64 %0, {%1,%2};" : "=l"(r) : "f"(a), "f"(b)); return r;
}
__device__ __forceinline__ void upk2(ull v, float& a, float& b) {
    asm("mov.b64 {%0,%1}, %2;" : "=f"(a), "=f"(b) : "l"(v));
}
__device__ __forceinline__ void fma2(ull& d, ull a, ull b) {
    asm("fma.rn.f32x2 %0, %1, %2, %0;" : "+l"(d) : "l"(a), "l"(b));
}
__device__ __forceinline__ unsigned tf32cvt(float f) {
    unsigned r; asm("cvt.rna.tf32.f32 %0, %1;" : "=r"(r) : "f"(f)); return r;
}
__device__ __forceinline__ void mma8(float* d, unsigned a0, unsigned a1, unsigned a2, unsigned a3,
                                     unsigned b0, unsigned b1) {
    asm volatile(
        "mma.sync.aligned.m16n8k8.row.col.f32.tf32.tf32.f32 "
        "{%0,%1,%2,%3}, {%4,%5,%6,%7}, {%8,%9}, {%0,%1,%2,%3};"
        : "+f"(d[0]), "+f"(d[1]), "+f"(d[2]), "+f"(d[3])
        : "r"(a0), "r"(a1), "r"(a2), "r"(a3), "r"(b0), "r"(b1));
}

// ---------------- generic SIMT GEMM infra ----------------
struct SmemG {
    float At[64][36];
    float Wt[32][128];
    float T1[64][132];
};

__device__ __forceinline__ void load_w_chunk(float* wt, const float* __restrict__ src, int tid) {
    #pragma unroll
    for (int j = 0; j < 4; j++) {
        int li = j * 1024 + tid * 4;
        *(float4*)&wt[li] = *(const float4*)(src + li);
    }
}
__device__ __forceinline__ void load_w_chunk_strided(float* wt, const float* __restrict__ base, int ldg, int tid) {
    #pragma unroll
    for (int j = 0; j < 4; j++) {
        int li = j * 1024 + tid * 4;
        int row = li >> 7, col = li & 127;
        *(float4*)&wt[li] = *(const float4*)(base + row * ldg + col);
    }
}

__device__ __forceinline__ void gemm_chunk(ull (&acc)[4][4],
                                           const float* a0, const float* a1,
                                           const float* a2, const float* a3,
                                           const float* wt, int c0) {
    #pragma unroll
    for (int kk = 0; kk < 32; kk += 4) {
        float4 A0 = *(const float4*)(a0 + kk);
        float4 A1 = *(const float4*)(a1 + kk);
        float4 A2 = *(const float4*)(a2 + kk);
        float4 A3 = *(const float4*)(a3 + kk);
        const float* w = wt + kk * 128 + c0;
        #pragma unroll
        for (int k4 = 0; k4 < 4; k4++) {
            ulonglong2 bA = *(const ulonglong2*)(w + k4 * 128);
            ulonglong2 bB = *(const ulonglong2*)(w + k4 * 128 + 64);
            float fa0 = (&A0.x)[k4], fa1 = (&A1.x)[k4];
            float fa2 = (&A2.x)[k4], fa3 = (&A3.x)[k4];
            ull p0 = pk2(fa0, fa0), p1 = pk2(fa1, fa1);
            ull p2 = pk2(fa2, fa2), p3 = pk2(fa3, fa3);
            fma2(acc[0][0], p0, bA.x); fma2(acc[0][1], p0, bA.y); fma2(acc[0][2], p0, bB.x); fma2(acc[0][3], p0, bB.y);
            fma2(acc[1][0], p1, bA.x); fma2(acc[1][1], p1, bA.y); fma2(acc[1][2], p1, bB.x); fma2(acc[1][3], p1, bB.y);
            fma2(acc[2][0], p2, bA.x); fma2(acc[2][1], p2, bA.y); fma2(acc[2][2], p2, bB.x); fma2(acc[2][3], p2, bB.y);
            fma2(acc[3][0], p3, bA.x); fma2(acc[3][1], p3, bA.y); fma2(acc[3][2], p3, bB.x); fma2(acc[3][3], p3, bB.y);
        }
    }
}
__device__ __forceinline__ void unpack_row(const ull* accr, float4& g0, float4& g1) {
    upk2(accr[0], g0.x, g0.y);
    upk2(accr[1], g0.z, g0.w);
    upk2(accr[2], g1.x, g1.y);
    upk2(accr[3], g1.z, g1.w);
}

// ---------------- kernels ----------------
__global__ void k_detect(const int* __restrict__ p) {
    if (threadIdx.x == 0) {
        int nz = 0;
        for (int i = 1; i < 128; i += 2) nz += (p[i] != 0);
        g_is64 = (nz == 0) ? 1 : 0;
    }
}

__global__ void k_premat(const float* __restrict__ xpw, const float* __restrict__ dtw) {
    int o = blockIdx.x * blockDim.x + threadIdx.x;
    int i = o >> 7, j = o & 127;
    float s = 0.f;
    #pragma unroll
    for (int r = 0; r < 8; r++) s += xpw[i * 136 + r] * dtw[r * 128 + j];
    g_M[o] = s;
}

// ---------- CSR build ----------
__global__ void k_zero_cnt(int Nn) {
    int i = blockIdx.x * blockDim.x + threadIdx.x;
    if (i < Nn) { g_cnt_r[i] = 0; g_cnt_c[i] = 0; g_cur_r[i] = 0; g_cur_c[i] = 0; }
}

__global__ void k_hist(const void* __restrict__ eidx, int E) {
    int e = blockIdx.x * blockDim.x + threadIdx.x;
    if (e >= E) return;
    int r, c;
    if (g_is64) {
        const long long* q = (const long long*)eidx;
        r = (int)q[e]; c = (int)q[(size_t)E + e];
    } else {
        const int* q = (const int*)eidx;
        r = q[e]; c = q[E + e];
    }
    atomicAdd(&g_cnt_r[r], 1);
    atomicAdd(&g_cnt_c[c], 1);
}

__global__ __launch_bounds__(1024) void k_scan_off(int Nn) {
    const int* cnt = blockIdx.x ? g_cnt_c : g_cnt_r;
    int* off = blockIdx.x ? g_off_c : g_off_r;
    __shared__ int sums[1024];
    int t = threadIdx.x;
    int chunk = (Nn + 1023) / 1024;
    int lo = t * chunk, hi = min(lo + chunk, Nn);
    int s = 0;
    for (int i = lo; i < hi; i++) s += cnt[i];
    sums[t] = s;
    __syncthreads();
    for (int d = 1; d < 1024; d <<= 1) {
        int v = (t >= d) ? sums[t - d] : 0;
        __syncthreads();
        sums[t] += v;
        __syncthreads();
    }
    int run = (t > 0) ? sums[t - 1] : 0;
    for (int i = lo; i < hi; i++) { off[i] = run; run += cnt[i]; }
    if (t == 1023) off[Nn] = run;
}

__global__ void k_fill(const void* __restrict__ eidx, int E) {
    int e = blockIdx.x * blockDim.x + threadIdx.x;
    if (e >= E) return;
    int r, c;
    if (g_is64) {
        const long long* q = (const long long*)eidx;
        r = (int)q[e]; c = (int)q[(size_t)E + e];
    } else {
        const int* q = (const int*)eidx;
        r = q[e]; c = q[E + e];
    }
    int pr = g_off_r[r] + atomicAdd(&g_cur_r[r], 1);
    g_eid_r[pr] = e;
    int pc = g_off_c[c] + atomicAdd(&g_cur_c[c], 1);
    g_eid_c[pc] = e;
}

// ---------- gather: agg (row-CSR) and mi (col-CSR) ----------
__global__ __launch_bounds__(256) void k_gather(int Nn) {
    int node = blockIdx.x * 2 + (threadIdx.x >> 7);
    int c = threadIdx.x & 127;
    if (node >= Nn) return;
    float acc = 0.f;
    {
        int b = g_off_r[node], en = g_off_r[node + 1];
        for (int i0 = b; i0 < en; i0 += 8) {
            int m = en - i0; if (m > 8) m = 8;
            int eids[8];
            #pragma unroll
            for (int j = 0; j < 8; j++) if (j < m) eids[j] = __ldg(&g_eid_r[i0 + j]);
            #pragma unroll
            for (int j = 0; j < 8; j++) if (j < m) acc += __ldg(&g_mij[(size_t)eids[j] * H + c]);
        }
        g_agg[(size_t)node * H + c] = acc;
    }
    {
        float acm = 0.f;
        int b = g_off_c[node], en = g_off_c[node + 1];
        for (int i0 = b; i0 < en; i0 += 8) {
            int m = en - i0; if (m > 8) m = 8;
            int eids[8];
            float ws[8];
            #pragma unroll
            for (int j = 0; j < 8; j++) if (j < m) eids[j] = __ldg(&g_eid_c[i0 + j]);
            #pragma unroll
            for (int j = 0; j < 8; j++) if (j < m) ws[j] = __ldg(&g_eij[eids[j]]);
            #pragma unroll
            for (int j = 0; j < 8; j++) if (j < m) acm += ws[j] * __ldg(&g_mij[(size_t)eids[j] * H + c]);
        }
        g_mi[(size_t)node * H + c] = acm;
    }
}

// P = h @ W1[0:128], Q = h @ W1[128:256]
__global__ __launch_bounds__(256, 3) void k_pq(
    const float* __restrict__ h, const float* __restrict__ W1, int Nn) {
    extern __shared__ char sraw[];
    SmemG& S = *(SmemG*)sraw;
    int tid = threadIdx.x;
    int row0 = blockIdx.x * 64;
    int tx = tid & 15, ty = tid >> 4;
    int c0 = tx * 4, r0 = ty * 4;
    for (int it = 0; it < 32; ++it) {
        int lin = it * 256 + tid;
        int r = lin >> 7, c = lin & 127;
        int node = min(row0 + r, Nn - 1);
        S.T1[r][c] = h[(size_t)node * H + c];
    }
    __syncthreads();
    for (int tgt = 0; tgt < 2; tgt++) {
        ull acc[4][4] = {};
        for (int kc = 0; kc < 128; kc += 32) {
            load_w_chunk(&S.Wt[0][0], W1 + (tgt * 128 + kc) * H, tid);
            __syncthreads();
            gemm_chunk(acc, &S.T1[r0][kc], &S.T1[r0 + 1][kc], &S.T1[r0 + 2][kc], &S.T1[r0 + 3][kc], &S.Wt[0][0], c0);
            __syncthreads();
        }
        float* dst = tgt ? g_Q : g_P;
        #pragma unroll
        for (int i = 0; i < 4; i++) {
            int node = row0 + r0 + i;
            if (node < Nn) {
                float4 g0, g1;
                unpack_row(acc[i], g0, g1);
                *(float4*)(dst + (size_t)node * H + c0)      = g0;
                *(float4*)(dst + (size_t)node * H + c0 + 64) = g1;
            }
        }
    }
}

// -------- edge kernel: stage-2 GEMM via mma.sync tf32, streaming outputs --------
#define ET 32

struct SmemE {
    float As[ET][132];
    int   rs[ET];
    int   cs[ET];
    float ea0[ET], ea1[ET];
    float wc0[H], wc1[H], b1s[H], b2s[H], infs[H];
    float dot[ET];
};

__global__ __launch_bounds__(256, 2) void k_edge_mma(
    const void* __restrict__ eidx, const float* __restrict__ eattr,
    const float* __restrict__ W1, const float* __restrict__ b1,
    const float* __restrict__ W2, const float* __restrict__ b2,
    const float* __restrict__ infw, const float* __restrict__ infb,
    int E, int ntiles) {
    __shared__ SmemE S;
    int tid = threadIdx.x;
    int lane = tid & 31, wid = tid >> 5;
    int gid = lane >> 2, tig = lane & 3;
    int is64 = g_is64;

    if (tid < H) {
        S.wc0[tid]  = W1[256 * H + tid];
        S.wc1[tid]  = W1[257 * H + tid];
        S.b1s[tid]  = b1[tid];
        S.b2s[tid]  = b2[tid];
        S.infs[tid] = infw[tid];
    }
    float infb0 = infb[0];

    // preload W2^T fragments for this warp's 16-col N-slice (tf32)
    int nb = wid * 16;
    unsigned bf[16][2][2];
    #pragma unroll
    for (int ks = 0; ks < 16; ks++) {
        #pragma unroll
        for (int nt = 0; nt < 2; nt++) {
            int k0 = ks * 8 + tig;
            int n = nb + nt * 8 + gid;
            bf[ks][nt][0] = tf32cvt(W2[k0 * H + n]);
            bf[ks][nt][1] = tf32cvt(W2[(k0 + 4) * H + n]);
        }
    }
    __syncthreads();

    int gr = tid >> 3, gc = (tid & 7) * 16;

    for (int tile = blockIdx.x; tile < ntiles; tile += gridDim.x) {
        int t0 = tile * ET;
        if (tid < ET) {
            int e = min(t0 + tid, E - 1);
            int r, c;
            if (is64) {
                const long long* q = (const long long*)eidx;
                r = (int)q[e]; c = (int)q[(size_t)E + e];
            } else {
                const int* q = (const int*)eidx;
                r = q[e]; c = q[E + e];
            }
            S.rs[tid] = r; S.cs[tid] = c;
            S.ea0[tid] = eattr[2 * e];
            S.ea1[tid] = eattr[2 * e + 1];
            S.dot[tid] = 0.f;
        }
        __syncthreads();

        // gather: 8 threads per row, 16 cols each
        {
            const float* Pr = g_P + (size_t)S.rs[gr] * H;
            const float* Qr = g_Q + (size_t)S.cs[gr] * H;
            float e0 = S.ea0[gr], e1 = S.ea1[gr];
            #pragma unroll
            for (int j = 0; j < 4; j++) {
                int c = gc + j * 4;
                float4 pv = *(const float4*)(Pr + c);
                float4 qv = *(const float4*)(Qr + c);
                float4 o;
                #pragma unroll
                for (int jj = 0; jj < 4; jj++) {
                    float v = (&pv.x)[jj] + (&qv.x)[jj]
                            + e0 * S.wc0[c + jj] + e1 * S.wc1[c + jj] + S.b1s[c + jj];
                    (&o.x)[jj] = silu(v);
                }
                *(float4*)&S.As[gr][c] = o;
            }
        }
        __syncthreads();

        // MMA: each warp computes 32 rows x its 16 cols
        float acc[2][2][4];
        #pragma unroll
        for (int mg = 0; mg < 2; mg++)
            #pragma unroll
            for (int nt = 0; nt < 2; nt++)
                #pragma unroll
                for (int j = 0; j < 4; j++) acc[mg][nt][j] = 0.f;
        #pragma unroll
        for (int mg = 0; mg < 2; mg++) {
            int ar = mg * 16 + gid;
            #pragma unroll
            for (int ks = 0; ks < 16; ks++) {
                int ac = ks * 8 + tig;
                unsigned a0 = tf32cvt(S.As[ar][ac]);
                unsigned a1 = tf32cvt(S.As[ar + 8][ac]);
                unsigned a2 = tf32cvt(S.As[ar][ac + 4]);
                unsigned a3 = tf32cvt(S.As[ar + 8][ac + 4]);
                mma8(acc[mg][0], a0, a1, a2, a3, bf[ks][0][0], bf[ks][0][1]);
                mma8(acc[mg][1], a0, a1, a2, a3, bf[ks][1][0], bf[ks][1][1]);
            }
        }

        // inf-gate dot partials (quad-reduce, then smem atomic)
        #pragma unroll
        for (int mg = 0; mg < 2; mg++) {
            int r0 = mg * 16 + gid, r1 = r0 + 8;
            float p0 = 0.f, p1 = 0.f;
            #pragma unroll
            for (int nt = 0; nt < 2; nt++) {
                int c = nb + nt * 8 + 2 * tig;
                float i0 = S.infs[c], i1 = S.infs[c + 1];
                float v0 = silu(acc[mg][nt][0] + S.b2s[c]);
                float v1 = silu(acc[mg][nt][1] + S.b2s[c + 1]);
                float v2 = silu(acc[mg][nt][2] + S.b2s[c]);
                float v3 = silu(acc[mg][nt][3] + S.b2s[c + 1]);
                p0 += v0 * i0 + v1 * i1;
                p1 += v2 * i0 + v3 * i1;
            }
            p0 += __shfl_xor_sync(0xffffffffu, p0, 1, 4);
            p0 += __shfl_xor_sync(0xffffffffu, p0, 2, 4);
            p1 += __shfl_xor_sync(0xffffffffu, p1, 1, 4);
            p1 += __shfl_xor_sync(0xffffffffu, p1, 2, 4);
            if (tig == 0) {
                atomicAdd(&S.dot[r0], p0);
                atomicAdd(&S.dot[r1], p1);
            }
        }
        __syncthreads();
        if (tid < ET && t0 + tid < E)
            g_eij[t0 + tid] = sigm(S.dot[tid] + infb0);

        // stream mij fragments to global (silu applied)
        #pragma unroll
        for (int mg = 0; mg < 2; mg++) {
            int r0 = mg * 16 + gid, r1 = r0 + 8;
            #pragma unroll
            for (int nt = 0; nt < 2; nt++) {
                int c = nb + nt * 8 + 2 * tig;
                float v0 = silu(acc[mg][nt][0] + S.b2s[c]);
                float v1 = silu(acc[mg][nt][1] + S.b2s[c + 1]);
                float v2 = silu(acc[mg][nt][2] + S.b2s[c]);
                float v3 = silu(acc[mg][nt][3] + S.b2s[c + 1]);
                if (t0 + r0 < E) *(float2*)(g_mij + (size_t)(t0 + r0) * H + c) = make_float2(v0, v1);
                if (t0 + r1 < E) *(float2*)(g_mij + (size_t)(t0 + r1) * H + c) = make_float2(v2, v3);
            }
        }
        __syncthreads();
    }
}

// h1 = h + nodeMLP([h, agg])
__global__ __launch_bounds__(256, 3) void k_node1(
    const float* __restrict__ h,
    const float* __restrict__ W1, const float* __restrict__ b1v,
    const float* __restrict__ W2, const float* __restrict__ b2v, int Nn) {
    extern __shared__ char sraw[];
    SmemG& S = *(SmemG*)sraw;
    int tid = threadIdx.x;
    int row0 = blockIdx.x * 64;
    int tx = tid & 15, ty = tid >> 4;
    int c0 = tx * 4, r0 = ty * 4;
    int le = tid >> 2, lk = (tid & 3) * 8;
    int node_l = min(row0 + le, Nn - 1);
    ull acc[4][4] = {};
    for (int kc = 0; kc < 256; kc += 32) {
        const float* srcb = (kc < 128) ? h : g_agg;
        const float* src = srcb + (size_t)node_l * H + (kc & 127) + lk;
        *(float4*)&S.At[le][lk]     = *(const float4*)src;
        *(float4*)&S.At[le][lk + 4] = *(const float4*)(src + 4);
        load_w_chunk(&S.Wt[0][0], W1 + kc * H, tid);
        __syncthreads();
        gemm_chunk(acc, &S.At[r0][0], &S.At[r0 + 1][0], &S.At[r0 + 2][0], &S.At[r0 + 3][0], &S.Wt[0][0], c0);
        __syncthreads();
    }
    #pragma unroll
    for (int i = 0; i < 4; i++) {
        float4 g0, g1;
        unpack_row(acc[i], g0, g1);
        float4 s0, s1;
        #pragma unroll
        for (int j = 0; j < 4; j++) {
            (&s0.x)[j] = silu((&g0.x)[j] + b1v[c0 + j]);
            (&s1.x)[j] = silu((&g1.x)[j] + b1v[c0 + 64 + j]);
        }
        *(float4*)&S.T1[r0 + i][c0]      = s0;
        *(float4*)&S.T1[r0 + i][c0 + 64] = s1;
        #pragma unroll
        for (int j = 0; j < 4; j++) acc[i][j] = 0ull;
    }
    __syncthreads();
    for (int kc = 0; kc < 128; kc += 32) {
        load_w_chunk(&S.Wt[0][0], W2 + kc * H, tid);
        __syncthreads();
        gemm_chunk(acc, &S.T1[r0][kc], &S.T1[r0 + 1][kc], &S.T1[r0 + 2][kc], &S.T1[r0 + 3][kc], &S.Wt[0][0], c0);
        __syncthreads();
    }
    #pragma unroll
    for (int i = 0; i < 4; i++) {
        int node = row0 + r0 + i;
        if (node < Nn) {
            float4 g0, g1;
            unpack_row(acc[i], g0, g1);
            const float* hr = h + (size_t)node * H;
            float4 h0 = *(const float4*)(hr + c0);
            float4 h1 = *(const float4*)(hr + c0 + 64);
            float4 o0, o1;
            #pragma unroll
            for (int j = 0; j < 4; j++) {
                (&o0.x)[j] = (&g0.x)[j] + b2v[c0 + j]      + (&h0.x)[j];
                (&o1.x)[j] = (&g1.x)[j] + b2v[c0 + 64 + j] + (&h1.x)[j];
            }
            *(float4*)(g_h1 + (size_t)node * H + c0)      = o0;
            *(float4*)(g_h1 + (size_t)node * H + c0 + 64) = o1;
        }
    }
}

// h2 = nodeMLP([mi, h1]);  xz = h2 @ in_proj_w ; split into g_x, g_z
__global__ __launch_bounds__(256, 3) void k_node2(
    const float* __restrict__ W1, const float* __restrict__ b1v,
    const float* __restrict__ W2, const float* __restrict__ b2v,
    const float* __restrict__ inpw, int Nn) {
    extern __shared__ char sraw[];
    SmemG& S = *(SmemG*)sraw;
    int tid = threadIdx.x;
    int row0 = blockIdx.x * 64;
    int tx = tid & 15, ty = tid >> 4;
    int c0 = tx * 4, r0 = ty * 4;
    int le = tid >> 2, lk = (tid & 3) * 8;
    int node_l = min(row0 + le, Nn - 1);
    ull acc[4][4] = {};
    for (int kc = 0; kc < 256; kc += 32) {
        const float* srcb = (kc < 128) ? g_mi : g_h1;
        const float* src = srcb + (size_t)node_l * H + (kc & 127) + lk;
        *(float4*)&S.At[le][lk]     = *(const float4*)src;
        *(float4*)&S.At[le][lk + 4] = *(const float4*)(src + 4);
        load_w_chunk(&S.Wt[0][0], W1 + kc * H, tid);
        __syncthreads();
        gemm_chunk(acc, &S.At[r0][0], &S.At[r0 + 1][0], &S.At[r0 + 2][0], &S.At[r0 + 3][0], &S.Wt[0][0], c0);
        __syncthreads();
    }
    #pragma unroll
    for (int i = 0; i < 4; i++) {
        float4 g0, g1;
        unpack_row(acc[i], g0, g1);
        float4 s0, s1;
        #pragma unroll
        for (int j = 0; j < 4; j++) {
            (&s0.x)[j] = silu((&g0.x)[j] + b1v[c0 + j]);
            (&s1.x)[j] = silu((&g1.x)[j] + b1v[c0 + 64 + j]);
        }
        *(float4*)&S.T1[r0 + i][c0]      = s0;
        *(float4*)&S.T1[r0 + i][c0 + 64] = s1;
        #pragma unroll
        for (int j = 0; j < 4; j++) acc[i][j] = 0ull;
    }
    __syncthreads();
    for (int kc = 0; kc < 128; kc += 32) {
        load_w_chunk(&S.Wt[0][0], W2 + kc * H, tid);
        __syncthreads();
        gemm_chunk(acc, &S.T1[r0][kc], &S.T1[r0 + 1][kc], &S.T1[r0 + 2][kc], &S.T1[r0 + 3][kc], &S.Wt[0][0], c0);
        __syncthreads();
    }
    float h2v[4][8];
    #pragma unroll
    for (int i = 0; i < 4; i++) {
        float4 g0, g1;
        unpack_row(acc[i], g0, g1);
        #pragma unroll
        for (int j = 0; j < 4; j++) {
            h2v[i][j]     = (&g0.x)[j] + b2v[c0 + j];
            h2v[i][4 + j] = (&g1.x)[j] + b2v[c0 + 64 + j];
        }
    }
    __syncthreads();
    #pragma unroll
    for (int i = 0; i < 4; i++) {
        *(float4*)&S.T1[r0 + i][c0]      = *(float4*)&h2v[i][0];
        *(float4*)&S.T1[r0 + i][c0 + 64] = *(float4*)&h2v[i][4];
    }
    __syncthreads();
    for (int half = 0; half < 2; half++) {
        #pragma unroll
        for (int i = 0; i < 4; i++)
            #pragma unroll
            for (int j = 0; j < 4; j++) acc[i][j] = 0ull;
        for (int kc = 0; kc < 128; kc += 32) {
            load_w_chunk_strided(&S.Wt[0][0], inpw + kc * 256 + half * 128, 256, tid);
            __syncthreads();
            gemm_chunk(acc, &S.T1[r0][kc], &S.T1[r0 + 1][kc], &S.T1[r0 + 2][kc], &S.T1[r0 + 3][kc], &S.Wt[0][0], c0);
            __syncthreads();
        }
        float* dst = half ? g_z : g_x;
        #pragma unroll
        for (int i = 0; i < 4; i++) {
            int node = row0 + r0 + i;
            if (node < Nn) {
                float4 g0, g1;
                unpack_row(acc[i], g0, g1);
                *(float4*)(dst + (size_t)node * H + c0)      = g0;
                *(float4*)(dst + (size_t)node * H + c0 + 64) = g1;
            }
        }
    }
}

// conv + silu -> xs ; B,C = xs @ x_proj_w[:,8:136] ; delta = softplus(xs @ M + dt_b)
__global__ __launch_bounds__(256, 3) void k_conv_proj(
    const float* __restrict__ xpw, const float* __restrict__ convw,
    const float* __restrict__ convb, const float* __restrict__ dtb, int Nn) {
    extern __shared__ char sraw[];
    SmemG& S = *(SmemG*)sraw;
    int tid = threadIdx.x;
    int row0 = blockIdx.x * 64;
    int tx = tid & 15, ty = tid >> 4;
    int c0 = tx * 4, r0 = ty * 4;
    for (int it = 0; it < 32; ++it) {
        int lin = it * 256 + tid;
        int r = lin >> 7, c = lin & 127;
        int node = row0 + r;
        float v = 0.f;
        if (node < Nn) {
            float a = convb[c];
            #pragma unroll
            for (int k = 0; k < 4; k++) {
                int t = node - 3 + k;
                if (t >= 0) a += convw[k * H + c] * g_x[(size_t)t * H + c];
            }
            v = silu(a);
            g_xs[(size_t)node * H + c] = v;
        }
        S.T1[r][c] = v;
    }
    __syncthreads();
    ull acc[4][4] = {};
    for (int kc = 0; kc < 128; kc += 32) {
        load_w_chunk_strided(&S.Wt[0][0], xpw + kc * 136 + 8, 136, tid);
        __syncthreads();
        gemm_chunk(acc, &S.T1[r0][kc], &S.T1[r0 + 1][kc], &S.T1[r0 + 2][kc], &S.T1[r0 + 3][kc], &S.Wt[0][0], c0);
        __syncthreads();
    }
    #pragma unroll
    for (int i = 0; i < 4; i++) {
        int node = row0 + r0 + i;
        if (node < Nn) {
            float4 g0, g1;
            unpack_row(acc[i], g0, g1);
            *(float4*)(g_Bm + (size_t)node * DS + c0) = g0;
            *(float4*)(g_Cm + (size_t)node * DS + c0) = g1;
        }
        #pragma unroll
        for (int j = 0; j < 4; j++) acc[i][j] = 0ull;
    }
    for (int kc = 0; kc < 128; kc += 32) {
        load_w_chunk(&S.Wt[0][0], g_M + kc * H, tid);
        __syncthreads();
        gemm_chunk(acc, &S.T1[r0][kc], &S.T1[r0 + 1][kc], &S.T1[r0 + 2][kc], &S.T1[r0 + 3][kc], &S.Wt[0][0], c0);
        __syncthreads();
    }
    #pragma unroll
    for (int i = 0; i < 4; i++) {
        int node = row0 + r0 + i;
        if (node < Nn) {
            float4 g0, g1;
            unpack_row(acc[i], g0, g1);
            float4 o0, o1;
            #pragma unroll
            for (int j = 0; j < 4; j++) {
                (&o0.x)[j] = softplus((&g0.x)[j] + dtb[c0 + j]);
                (&o1.x)[j] = softplus((&g1.x)[j] + dtb[c0 + 64 + j]);
            }
            *(float4*)(g_delta + (size_t)node * H + c0)      = o0;
            *(float4*)(g_delta + (size_t)node * H + c0 + 64) = o1;
        }
    }
}

// chunked selective scan, phase A
__global__ void k_scanA(const float* __restrict__ A_log, int Nn) {
    int warp = threadIdx.x >> 5;
    int lane = threadIdx.x & 31;
    int c = blockIdx.x;
    int hch = blockIdx.y * 8 + warp;
    int s0 = lane, s1 = lane + 32;
    float A0 = -__expf(A_log[hch * DS + s0]);
    float A1 = -__expf(A_log[hch * DS + s1]);
    float hc0 = 0.f, hc1 = 0.f, dsum = 0.f;
    int t0 = c * TCH, t1 = min(Nn, t0 + TCH);
    for (int t = t0; t < t1; ++t) {
        float d = __ldg(&g_delta[(size_t)t * H + hch]);
        float xv = __ldg(&g_xs[(size_t)t * H + hch]);
        float b0 = g_Bm[(size_t)t * DS + s0];
        float b1v = g_Bm[(size_t)t * DS + s1];
        float dx = d * xv;
        hc0 = __expf(d * A0) * hc0 + dx * b0;
        hc1 = __expf(d * A1) * hc1 + dx * b1v;
        dsum += d;
    }
    size_t o = ((size_t)c * H + hch) * DS;
    g_bstate[o + s0] = hc0;
    g_bstate[o + s1] = hc1;
    g_aprod[o + s0] = __expf(A0 * dsum);
    g_aprod[o + s1] = __expf(A1 * dsum);
}

// phase B
__global__ void k_prefix(int NC) {
    int hs = blockIdx.x * blockDim.x + threadIdx.x;
    float st = 0.f;
    for (int c = 0; c < NC; c++) {
        size_t o = (size_t)c * (H * DS) + hs;
        g_sstart[o] = st;
        st = g_aprod[o] * st + g_bstate[o];
    }
}

// phase C
__global__ void k_scanC(const float* __restrict__ A_log, const float* __restrict__ Dv, int Nn) {
    int warp = threadIdx.x >> 5;
    int lane = threadIdx.x & 31;
    int c = blockIdx.x;
    int hch = blockIdx.y * 8 + warp;
    int s0 = lane, s1 = lane + 32;
    float A0 = -__expf(A_log[hch * DS + s0]);
    float A1 = -__expf(A_log[hch * DS + s1]);
    size_t o = ((size_t)c * H + hch) * DS;
    float hc0 = g_sstart[o + s0];
    float hc1 = g_sstart[o + s1];
    float dh = Dv[hch];
    int t0 = c * TCH, t1 = min(Nn, t0 + TCH);
    for (int t = t0; t < t1; ++t) {
        float d = __ldg(&g_delta[(size_t)t * H + hch]);
        float xv = __ldg(&g_xs[(size_t)t * H + hch]);
        float b0 = g_Bm[(size_t)t * DS + s0];
        float b1v = g_Bm[(size_t)t * DS + s1];
        float c0 = g_Cm[(size_t)t * DS + s0];
        float c1 = g_Cm[(size_t)t * DS + s1];
        float dx = d * xv;
        hc0 = __expf(d * A0) * hc0 + dx * b0;
        hc1 = __expf(d * A1) * hc1 + dx * b1v;
        float p = hc0 * c0 + hc1 * c1;
        #pragma unroll
        for (int off = 16; off; off >>= 1) p += __shfl_down_sync(0xffffffffu, p, off);
        if (lane == 0) {
            float zv = g_z[(size_t)t * H + hch];
            g_y[(size_t)t * H + hch] = (p + dh * xv) * zv * sigm(zv);
        }
    }
}

// out = y @ out_proj_w
__global__ __launch_bounds__(256, 3) void k_out(const float* __restrict__ W, float* __restrict__ out, int Nn) {
    extern __shared__ char sraw[];
    SmemG& S = *(SmemG*)sraw;
    int tid = threadIdx.x;
    int row0 = blockIdx.x * 64;
    int tx = tid & 15, ty = tid >> 4;
    int c0 = tx * 4, r0 = ty * 4;
    for (int it = 0; it < 32; ++it) {
        int lin = it * 256 + tid;
        int r = lin >> 7, c = lin & 127;
        int node = min(row0 + r, Nn - 1);
        S.T1[r][c] = g_y[(size_t)node * H + c];
    }
    __syncthreads();
    ull acc[4][4] = {};
    for (int kc = 0; kc < 128; kc += 32) {
        load_w_chunk(&S.Wt[0][0], W + kc * H, tid);
        __syncthreads();
        gemm_chunk(acc, &S.T1[r0][kc], &S.T1[r0 + 1][kc], &S.T1[r0 + 2][kc], &S.T1[r0 + 3][kc], &S.Wt[0][0], c0);
        __syncthreads();
    }
    #pragma unroll
    for (int i = 0; i < 4; i++) {
        int node = row0 + r0 + i;
        if (node < Nn) {
            float4 g0, g1;
            unpack_row(acc[i], g0, g1);
            *(float4*)(out + (size_t)node * H + c0)      = g0;
            *(float4*)(out + (size_t)node * H + c0 + 64) = g1;
        }
    }
}

// ---------------- launch ----------------
extern "C" void kernel_launch(void* const* d_in, const int* in_sizes, int n_in,
                              void* d_out, int out_size) {
    const float* h      = (const float*)d_in[0];
    const void*  eidx   = d_in[1];
    const float* eattr  = (const float*)d_in[2];
    const float* e_w1   = (const float*)d_in[3];
    const float* e_b1   = (const float*)d_in[4];
    const float* e_w2   = (const float*)d_in[5];
    const float* e_b2   = (const float*)d_in[6];
    const float* inf_w  = (const float*)d_in[7];
    const float* inf_b  = (const float*)d_in[8];
    const float* n_w1   = (const float*)d_in[9];
    const float* n_b1   = (const float*)d_in[10];
    const float* n_w2   = (const float*)d_in[11];
    const float* n_b2   = (const float*)d_in[12];
    const float* in_prj = (const float*)d_in[13];
    const float* conv_w = (const float*)d_in[14];
    const float* conv_b = (const float*)d_in[15];
    const float* x_proj = (const float*)d_in[16];
    const float* dt_w   = (const float*)d_in[17];
    const float* dt_b   = (const float*)d_in[18];
    const float* A_log  = (const float*)d_in[19];
    const float* Dv     = (const float*)d_in[20];
    const float* out_w  = (const float*)d_in[21];

    int Nn = in_sizes[0] / H;
    int E  = in_sizes[2] / 2;
    int NC = (Nn + TCH - 1) / TCH;
    int nb = (Nn + 63) / 64;
    int ntiles = (E + ET - 1) / ET;
    int smemG = (int)sizeof(SmemG);

    cudaFuncSetAttribute(k_pq,        cudaFuncAttributeMaxDynamicSharedMemorySize, smemG);
    cudaFuncSetAttribute(k_node1,     cudaFuncAttributeMaxDynamicSharedMemorySize, smemG);
    cudaFuncSetAttribute(k_node2,     cudaFuncAttributeMaxDynamicSharedMemorySize, smemG);
    cudaFuncSetAttribute(k_conv_proj, cudaFuncAttributeMaxDynamicSharedMemorySize, smemG);
    cudaFuncSetAttribute(k_out,       cudaFuncAttributeMaxDynamicSharedMemorySize, smemG);

    k_detect<<<1, 32>>>((const int*)eidx);
    k_premat<<<64, 256>>>(x_proj, dt_w);
    // CSR build
    k_zero_cnt<<<(Nn + 255) / 256, 256>>>(Nn);
    k_hist<<<(E + 255) / 256, 256>>>(eidx, E);
    k_scan_off<<<2, 1024>>>(Nn);
    k_fill<<<(E + 255) / 256, 256>>>(eidx, E);
    // edge pipeline
    k_pq<<<nb, 256, smemG>>>(h, e_w1, Nn);
    int egrid = ntiles < 296 ? ntiles : 296;
    k_edge_mma<<<egrid, 256>>>(eidx, eattr, e_w1, e_b1, e_w2, e_b2, inf_w, inf_b, E, ntiles);
    k_gather<<<(Nn + 1) / 2, 256>>>(Nn);
    // node + mamba pipeline
    k_node1<<<nb, 256, smemG>>>(h, n_w1, n_b1, n_w2, n_b2, Nn);
    k_node2<<<nb, 256, smemG>>>(n_w1, n_b1, n_w2, n_b2, in_prj, Nn);
    k_conv_proj<<<nb, 256, smemG>>>(x_proj, conv_w, conv_b, dt_b, Nn);
    dim3 gs(NC, 16);
    k_scanA<<<gs, 256>>>(A_log, Nn);
    k_prefix<<<32, 256>>>(NC);
    k_scanC<<<gs, 256>>>(A_log, Dv, Nn);
    k_out<<<nb, 256, smemG>>>(out_w, (float*)d_out, Nn);
}

// round 7
// speedup vs baseline: 1.1691x; 1.1691x over previous
#include <cuda_runtime.h>
#include <cuda_fp16.h>
#include <math.h>

#define H 128
#define DS 64
#define TCH 128
#define MAXN 20000
#define MAXE 640000
#define MAXNC 157

typedef unsigned long long ull;

// ---------------- scratch ----------------
__device__ float g_mi[MAXN * H];
__device__ float g_agg[MAXN * H];
__device__ float g_h1[MAXN * H];
__device__ float g_x[MAXN * H];
__device__ float g_z[MAXN * H];
__device__ float g_xs[MAXN * H];
__device__ float g_delta[MAXN * H];
__device__ float g_Bm[MAXN * DS];
__device__ float g_Cm[MAXN * DS];
__device__ float g_y[MAXN * H];
__device__ float g_P[MAXN * H];
__device__ float g_Q[MAXN * H];
__device__ float g_M[H * H];
__device__ float g_aprod[MAXNC * H * DS];
__device__ float g_bstate[MAXNC * H * DS];
__device__ float g_sstart[MAXNC * H * DS];
__device__ int   g_is64;
// edge materialization (fp16) + CSR
__device__ __half g_hij[MAXE * H];
__device__ float g_eij[MAXE];
__device__ int g_cnt_r[MAXN], g_cnt_c[MAXN], g_cur_r[MAXN], g_cur_c[MAXN];
__device__ int g_off_r[MAXN + 1], g_off_c[MAXN + 1];
__device__ int g_eid_r[MAXE], g_eid_c[MAXE];

// ---------------- helpers ----------------
__device__ __forceinline__ float sigm(float v) { return 1.f / (1.f + __expf(-v)); }
__device__ __forceinline__ float silu(float v) { return v / (1.f + __expf(-v)); }
__device__ __forceinline__ float softplus(float v) { return (v > 20.f) ? v : log1pf(__expf(v)); }

__device__ __forceinline__ ull pk2(float a, float b) {
    ull r; asm("mov.b64 %0, {%1,%2};" : "=l"(r) : "f"(a), "f"(b)); return r;
}
__device__ __forceinline__ void upk2(ull v, float& a, float& b) {
    asm("mov.b64 {%0,%1}, %2;" : "=f"(a), "=f"(b) : "l"(v));
}
__device__ __forceinline__ void fma2(ull& d, ull a, ull b) {
    asm("fma.rn.f32x2 %0, %1, %2, %0;" : "+l"(d) : "l"(a), "l"(b));
}
__device__ __forceinline__ unsigned tf32cvt(float f) {
    unsigned r; asm("cvt.rna.tf32.f32 %0, %1;" : "=r"(r) : "f"(f)); return r;
}
__device__ __forceinline__ void mma8(float* d, unsigned a0, unsigned a1, unsigned a2, unsigned a3,
                                     unsigned b0, unsigned b1) {
    asm volatile(
        "mma.sync.aligned.m16n8k8.row.col.f32.tf32.tf32.f32 "
        "{%0,%1,%2,%3}, {%4,%5,%6,%7}, {%8,%9}, {%0,%1,%2,%3};"
        : "+f"(d[0]), "+f"(d[1]), "+f"(d[2]), "+f"(d[3])
        : "r"(a0), "r"(a1), "r"(a2), "r"(a3), "r"(b0), "r"(b1));
}

// ---------------- generic SIMT GEMM infra ----------------
struct SmemG {
    float At[64][36];
    float Wt[32][128];
    float T1[64][132];
};

__device__ __forceinline__ void load_w_chunk(float* wt, const float* __restrict__ src, int tid) {
    #pragma unroll
    for (int j = 0; j < 4; j++) {
        int li = j * 1024 + tid * 4;
        *(float4*)&wt[li] = *(const float4*)(src + li);
    }
}
__device__ __forceinline__ void load_w_chunk_strided(float* wt, const float* __restrict__ base, int ldg, int tid) {
    #pragma unroll
    for (int j = 0; j < 4; j++) {
        int li = j * 1024 + tid * 4;
        int row = li >> 7, col = li & 127;
        *(float4*)&wt[li] = *(const float4*)(base + row * ldg + col);
    }
}

__device__ __forceinline__ void gemm_chunk(ull (&acc)[4][4],
                                           const float* a0, const float* a1,
                                           const float* a2, const float* a3,
                                           const float* wt, int c0) {
    #pragma unroll
    for (int kk = 0; kk < 32; kk += 4) {
        float4 A0 = *(const float4*)(a0 + kk);
        float4 A1 = *(const float4*)(a1 + kk);
        float4 A2 = *(const float4*)(a2 + kk);
        float4 A3 = *(const float4*)(a3 + kk);
        const float* w = wt + kk * 128 + c0;
        #pragma unroll
        for (int k4 = 0; k4 < 4; k4++) {
            ulonglong2 bA = *(const ulonglong2*)(w + k4 * 128);
            ulonglong2 bB = *(const ulonglong2*)(w + k4 * 128 + 64);
            float fa0 = (&A0.x)[k4], fa1 = (&A1.x)[k4];
            float fa2 = (&A2.x)[k4], fa3 = (&A3.x)[k4];
            ull p0 = pk2(fa0, fa0), p1 = pk2(fa1, fa1);
            ull p2 = pk2(fa2, fa2), p3 = pk2(fa3, fa3);
            fma2(acc[0][0], p0, bA.x); fma2(acc[0][1], p0, bA.y); fma2(acc[0][2], p0, bB.x); fma2(acc[0][3], p0, bB.y);
            fma2(acc[1][0], p1, bA.x); fma2(acc[1][1], p1, bA.y); fma2(acc[1][2], p1, bB.x); fma2(acc[1][3], p1, bB.y);
            fma2(acc[2][0], p2, bA.x); fma2(acc[2][1], p2, bA.y); fma2(acc[2][2], p2, bB.x); fma2(acc[2][3], p2, bB.y);
            fma2(acc[3][0], p3, bA.x); fma2(acc[3][1], p3, bA.y); fma2(acc[3][2], p3, bB.x); fma2(acc[3][3], p3, bB.y);
        }
    }
}
__device__ __forceinline__ void unpack_row(const ull* accr, float4& g0, float4& g1) {
    upk2(accr[0], g0.x, g0.y);
    upk2(accr[1], g0.z, g0.w);
    upk2(accr[2], g1.x, g1.y);
    upk2(accr[3], g1.z, g1.w);
}

// ---------------- kernels ----------------
__global__ void k_detect(const int* __restrict__ p) {
    if (threadIdx.x == 0) {
        int nz = 0;
        for (int i = 1; i < 128; i += 2) nz += (p[i] != 0);
        g_is64 = (nz == 0) ? 1 : 0;
    }
}

__global__ void k_premat(const float* __restrict__ xpw, const float* __restrict__ dtw) {
    int o = blockIdx.x * blockDim.x + threadIdx.x;
    int i = o >> 7, j = o & 127;
    float s = 0.f;
    #pragma unroll
    for (int r = 0; r < 8; r++) s += xpw[i * 136 + r] * dtw[r * 128 + j];
    g_M[o] = s;
}

// ---------- CSR build ----------
__global__ void k_zero_cnt(int Nn) {
    int i = blockIdx.x * blockDim.x + threadIdx.x;
    if (i < Nn) { g_cnt_r[i] = 0; g_cnt_c[i] = 0; g_cur_r[i] = 0; g_cur_c[i] = 0; }
}

__global__ void k_hist(const void* __restrict__ eidx, int E) {
    int e = blockIdx.x * blockDim.x + threadIdx.x;
    if (e >= E) return;
    int r, c;
    if (g_is64) {
        const long long* q = (const long long*)eidx;
        r = (int)q[e]; c = (int)q[(size_t)E + e];
    } else {
        const int* q = (const int*)eidx;
        r = q[e]; c = q[E + e];
    }
    atomicAdd(&g_cnt_r[r], 1);
    atomicAdd(&g_cnt_c[c], 1);
}

__global__ __launch_bounds__(1024) void k_scan_off(int Nn) {
    const int* cnt = blockIdx.x ? g_cnt_c : g_cnt_r;
    int* off = blockIdx.x ? g_off_c : g_off_r;
    __shared__ int sums[1024];
    int t = threadIdx.x;
    int chunk = (Nn + 1023) / 1024;
    int lo = t * chunk, hi = min(lo + chunk, Nn);
    int s = 0;
    for (int i = lo; i < hi; i++) s += cnt[i];
    sums[t] = s;
    __syncthreads();
    for (int d = 1; d < 1024; d <<= 1) {
        int v = (t >= d) ? sums[t - d] : 0;
        __syncthreads();
        sums[t] += v;
        __syncthreads();
    }
    int run = (t > 0) ? sums[t - 1] : 0;
    for (int i = lo; i < hi; i++) { off[i] = run; run += cnt[i]; }
    if (t == 1023) off[Nn] = run;
}

__global__ void k_fill(const void* __restrict__ eidx, int E) {
    int e = blockIdx.x * blockDim.x + threadIdx.x;
    if (e >= E) return;
    int r, c;
    if (g_is64) {
        const long long* q = (const long long*)eidx;
        r = (int)q[e]; c = (int)q[(size_t)E + e];
    } else {
        const int* q = (const int*)eidx;
        r = q[e]; c = q[E + e];
    }
    int pr = g_off_r[r] + atomicAdd(&g_cur_r[r], 1);
    g_eid_r[pr] = e;
    int pc = g_off_c[c] + atomicAdd(&g_cur_c[c], 1);
    g_eid_c[pc] = e;
}

// ---------- gather: 32-thread squad per node, 4 cols/thread via uint2 ----------
__global__ __launch_bounds__(256) void k_gather(int Nn) {
    int sq = threadIdx.x >> 5, lane = threadIdx.x & 31;
    int node = blockIdx.x * 8 + sq;
    if (node >= Nn) return;
    int cb = lane * 4;
    // row pass -> agg
    {
        float a0 = 0.f, a1 = 0.f, a2 = 0.f, a3 = 0.f;
        int b = g_off_r[node], en = g_off_r[node + 1];
        for (int i0 = b; i0 < en; i0 += 8) {
            int m = en - i0; if (m > 8) m = 8;
            int eid[8];
            #pragma unroll
            for (int j = 0; j < 8; j++) if (j < m) eid[j] = __ldg(&g_eid_r[i0 + j]);
            #pragma unroll
            for (int j = 0; j < 8; j++) if (j < m) {
                uint2 pv = *(const uint2*)(g_hij + (size_t)eid[j] * H + cb);
                float2 f0 = __half22float2(*(__half2*)&pv.x);
                float2 f1 = __half22float2(*(__half2*)&pv.y);
                a0 += f0.x; a1 += f0.y; a2 += f1.x; a3 += f1.y;
            }
        }
        *(float4*)(g_agg + (size_t)node * H + cb) = make_float4(a0, a1, a2, a3);
    }
    // col pass -> mi (weighted by eij)
    {
        float a0 = 0.f, a1 = 0.f, a2 = 0.f, a3 = 0.f;
        int b = g_off_c[node], en = g_off_c[node + 1];
        for (int i0 = b; i0 < en; i0 += 8) {
            int m = en - i0; if (m > 8) m = 8;
            int eid[8];
            float w[8];
            #pragma unroll
            for (int j = 0; j < 8; j++) if (j < m) eid[j] = __ldg(&g_eid_c[i0 + j]);
            #pragma unroll
            for (int j = 0; j < 8; j++) if (j < m) w[j] = __ldg(&g_eij[eid[j]]);
            #pragma unroll
            for (int j = 0; j < 8; j++) if (j < m) {
                uint2 pv = *(const uint2*)(g_hij + (size_t)eid[j] * H + cb);
                float2 f0 = __half22float2(*(__half2*)&pv.x);
                float2 f1 = __half22float2(*(__half2*)&pv.y);
                a0 += w[j] * f0.x; a1 += w[j] * f0.y; a2 += w[j] * f1.x; a3 += w[j] * f1.y;
            }
        }
        *(float4*)(g_mi + (size_t)node * H + cb) = make_float4(a0, a1, a2, a3);
    }
}

// P = h @ W1[0:128], Q = h @ W1[128:256]
__global__ __launch_bounds__(256, 3) void k_pq(
    const float* __restrict__ h, const float* __restrict__ W1, int Nn) {
    extern __shared__ char sraw[];
    SmemG& S = *(SmemG*)sraw;
    int tid = threadIdx.x;
    int row0 = blockIdx.x * 64;
    int tx = tid & 15, ty = tid >> 4;
    int c0 = tx * 4, r0 = ty * 4;
    for (int it = 0; it < 32; ++it) {
        int lin = it * 256 + tid;
        int r = lin >> 7, c = lin & 127;
        int node = min(row0 + r, Nn - 1);
        S.T1[r][c] = h[(size_t)node * H + c];
    }
    __syncthreads();
    for (int tgt = 0; tgt < 2; tgt++) {
        ull acc[4][4] = {};
        for (int kc = 0; kc < 128; kc += 32) {
            load_w_chunk(&S.Wt[0][0], W1 + (tgt * 128 + kc) * H, tid);
            __syncthreads();
            gemm_chunk(acc, &S.T1[r0][kc], &S.T1[r0 + 1][kc], &S.T1[r0 + 2][kc], &S.T1[r0 + 3][kc], &S.Wt[0][0], c0);
            __syncthreads();
        }
        float* dst = tgt ? g_Q : g_P;
        #pragma unroll
        for (int i = 0; i < 4; i++) {
            int node = row0 + r0 + i;
            if (node < Nn) {
                float4 g0, g1;
                unpack_row(acc[i], g0, g1);
                *(float4*)(dst + (size_t)node * H + c0)      = g0;
                *(float4*)(dst + (size_t)node * H + c0 + 64) = g1;
            }
        }
    }
}

// -------- edge kernel: stage-2 GEMM via mma.sync tf32; stream fp16 mij + fp32 eij --------
#define ET 32

struct SmemE {
    float As[ET][132];
    __half Hs[ET][136];
    int   rs[ET];
    int   cs[ET];
    float ea0[ET], ea1[ET];
    float wc0[H], wc1[H], b1s[H], b2s[H], infs[H];
    float dot[ET];
};

__global__ __launch_bounds__(256, 2) void k_edge_mma(
    const void* __restrict__ eidx, const float* __restrict__ eattr,
    const float* __restrict__ W1, const float* __restrict__ b1,
    const float* __restrict__ W2, const float* __restrict__ b2,
    const float* __restrict__ infw, const float* __restrict__ infb,
    int E, int ntiles) {
    __shared__ SmemE S;
    int tid = threadIdx.x;
    int lane = tid & 31, wid = tid >> 5;
    int gid = lane >> 2, tig = lane & 3;
    int is64 = g_is64;

    if (tid < H) {
        S.wc0[tid]  = W1[256 * H + tid];
        S.wc1[tid]  = W1[257 * H + tid];
        S.b1s[tid]  = b1[tid];
        S.b2s[tid]  = b2[tid];
        S.infs[tid] = infw[tid];
    }
    float infb0 = infb[0];

    // preload W2^T fragments for this warp's 16-col N-slice (tf32)
    int nb = wid * 16;
    unsigned bf[16][2][2];
    #pragma unroll
    for (int ks = 0; ks < 16; ks++) {
        #pragma unroll
        for (int nt = 0; nt < 2; nt++) {
            int k0 = ks * 8 + tig;
            int n = nb + nt * 8 + gid;
            bf[ks][nt][0] = tf32cvt(W2[k0 * H + n]);
            bf[ks][nt][1] = tf32cvt(W2[(k0 + 4) * H + n]);
        }
    }
    __syncthreads();

    int gr = tid >> 3, gc = (tid & 7) * 16;

    for (int tile = blockIdx.x; tile < ntiles; tile += gridDim.x) {
        int t0 = tile * ET;
        if (tid < ET) {
            int e = min(t0 + tid, E - 1);
            int r, c;
            if (is64) {
                const long long* q = (const long long*)eidx;
                r = (int)q[e]; c = (int)q[(size_t)E + e];
            } else {
                const int* q = (const int*)eidx;
                r = q[e]; c = q[E + e];
            }
            S.rs[tid] = r; S.cs[tid] = c;
            S.ea0[tid] = eattr[2 * e];
            S.ea1[tid] = eattr[2 * e + 1];
            S.dot[tid] = 0.f;
        }
        __syncthreads();

        // gather: 8 threads per row, 16 cols each
        {
            const float* Pr = g_P + (size_t)S.rs[gr] * H;
            const float* Qr = g_Q + (size_t)S.cs[gr] * H;
            float e0 = S.ea0[gr], e1 = S.ea1[gr];
            #pragma unroll
            for (int j = 0; j < 4; j++) {
                int c = gc + j * 4;
                float4 pv = *(const float4*)(Pr + c);
                float4 qv = *(const float4*)(Qr + c);
                float4 o;
                #pragma unroll
                for (int jj = 0; jj < 4; jj++) {
                    float v = (&pv.x)[jj] + (&qv.x)[jj]
                            + e0 * S.wc0[c + jj] + e1 * S.wc1[c + jj] + S.b1s[c + jj];
                    (&o.x)[jj] = silu(v);
                }
                *(float4*)&S.As[gr][c] = o;
            }
        }
        __syncthreads();

        // MMA: each warp computes 32 rows x its 16 cols
        float acc[2][2][4];
        #pragma unroll
        for (int mg = 0; mg < 2; mg++)
            #pragma unroll
            for (int nt = 0; nt < 2; nt++)
                #pragma unroll
                for (int j = 0; j < 4; j++) acc[mg][nt][j] = 0.f;
        #pragma unroll
        for (int mg = 0; mg < 2; mg++) {
            int ar = mg * 16 + gid;
            #pragma unroll
            for (int ks = 0; ks < 16; ks++) {
                int ac = ks * 8 + tig;
                unsigned a0 = tf32cvt(S.As[ar][ac]);
                unsigned a1 = tf32cvt(S.As[ar + 8][ac]);
                unsigned a2 = tf32cvt(S.As[ar][ac + 4]);
                unsigned a3 = tf32cvt(S.As[ar + 8][ac + 4]);
                mma8(acc[mg][0], a0, a1, a2, a3, bf[ks][0][0], bf[ks][0][1]);
                mma8(acc[mg][1], a0, a1, a2, a3, bf[ks][1][0], bf[ks][1][1]);
            }
        }

        // inf-gate dot partials (quad-reduce, then smem atomic) + fp16 staging
        #pragma unroll
        for (int mg = 0; mg < 2; mg++) {
            int r0 = mg * 16 + gid, r1 = r0 + 8;
            float p0 = 0.f, p1 = 0.f;
            #pragma unroll
            for (int nt = 0; nt < 2; nt++) {
                int c = nb + nt * 8 + 2 * tig;
                float i0 = S.infs[c], i1 = S.infs[c + 1];
                float v0 = silu(acc[mg][nt][0] + S.b2s[c]);
                float v1 = silu(acc[mg][nt][1] + S.b2s[c + 1]);
                float v2 = silu(acc[mg][nt][2] + S.b2s[c]);
                float v3 = silu(acc[mg][nt][3] + S.b2s[c + 1]);
                p0 += v0 * i0 + v1 * i1;
                p1 += v2 * i0 + v3 * i1;
                *(__half2*)&S.Hs[r0][c] = __floats2half2_rn(v0, v1);
                *(__half2*)&S.Hs[r1][c] = __floats2half2_rn(v2, v3);
            }
            p0 += __shfl_xor_sync(0xffffffffu, p0, 1, 4);
            p0 += __shfl_xor_sync(0xffffffffu, p0, 2, 4);
            p1 += __shfl_xor_sync(0xffffffffu, p1, 1, 4);
            p1 += __shfl_xor_sync(0xffffffffu, p1, 2, 4);
            if (tig == 0) {
                atomicAdd(&S.dot[r0], p0);
                atomicAdd(&S.dot[r1], p1);
            }
        }
        __syncthreads();
        if (tid < ET && t0 + tid < E)
            g_eij[t0 + tid] = sigm(S.dot[tid] + infb0);

        // coalesced copy-out of the fp16 tile: 32 rows x 256B
        {
            int r = tid >> 3;
            int cw = (tid & 7) * 16;
            if (t0 + r < E) {
                uint4 vA = *(uint4*)&S.Hs[r][cw];
                uint4 vB = *(uint4*)&S.Hs[r][cw + 8];
                *(uint4*)(g_hij + (size_t)(t0 + r) * H + cw)     = vA;
                *(uint4*)(g_hij + (size_t)(t0 + r) * H + cw + 8) = vB;
            }
        }
        __syncthreads();
    }
}

// h1 = h + nodeMLP([h, agg])
__global__ __launch_bounds__(256, 3) void k_node1(
    const float* __restrict__ h,
    const float* __restrict__ W1, const float* __restrict__ b1v,
    const float* __restrict__ W2, const float* __restrict__ b2v, int Nn) {
    extern __shared__ char sraw[];
    SmemG& S = *(SmemG*)sraw;
    int tid = threadIdx.x;
    int row0 = blockIdx.x * 64;
    int tx = tid & 15, ty = tid >> 4;
    int c0 = tx * 4, r0 = ty * 4;
    int le = tid >> 2, lk = (tid & 3) * 8;
    int node_l = min(row0 + le, Nn - 1);
    ull acc[4][4] = {};
    for (int kc = 0; kc < 256; kc += 32) {
        const float* srcb = (kc < 128) ? h : g_agg;
        const float* src = srcb + (size_t)node_l * H + (kc & 127) + lk;
        *(float4*)&S.At[le][lk]     = *(const float4*)src;
        *(float4*)&S.At[le][lk + 4] = *(const float4*)(src + 4);
        load_w_chunk(&S.Wt[0][0], W1 + kc * H, tid);
        __syncthreads();
        gemm_chunk(acc, &S.At[r0][0], &S.At[r0 + 1][0], &S.At[r0 + 2][0], &S.At[r0 + 3][0], &S.Wt[0][0], c0);
        __syncthreads();
    }
    #pragma unroll
    for (int i = 0; i < 4; i++) {
        float4 g0, g1;
        unpack_row(acc[i], g0, g1);
        float4 s0, s1;
        #pragma unroll
        for (int j = 0; j < 4; j++) {
            (&s0.x)[j] = silu((&g0.x)[j] + b1v[c0 + j]);
            (&s1.x)[j] = silu((&g1.x)[j] + b1v[c0 + 64 + j]);
        }
        *(float4*)&S.T1[r0 + i][c0]      = s0;
        *(float4*)&S.T1[r0 + i][c0 + 64] = s1;
        #pragma unroll
        for (int j = 0; j < 4; j++) acc[i][j] = 0ull;
    }
    __syncthreads();
    for (int kc = 0; kc < 128; kc += 32) {
        load_w_chunk(&S.Wt[0][0], W2 + kc * H, tid);
        __syncthreads();
        gemm_chunk(acc, &S.T1[r0][kc], &S.T1[r0 + 1][kc], &S.T1[r0 + 2][kc], &S.T1[r0 + 3][kc], &S.Wt[0][0], c0);
        __syncthreads();
    }
    #pragma unroll
    for (int i = 0; i < 4; i++) {
        int node = row0 + r0 + i;
        if (node < Nn) {
            float4 g0, g1;
            unpack_row(acc[i], g0, g1);
            const float* hr = h + (size_t)node * H;
            float4 h0 = *(const float4*)(hr + c0);
            float4 h1 = *(const float4*)(hr + c0 + 64);
            float4 o0, o1;
            #pragma unroll
            for (int j = 0; j < 4; j++) {
                (&o0.x)[j] = (&g0.x)[j] + b2v[c0 + j]      + (&h0.x)[j];
                (&o1.x)[j] = (&g1.x)[j] + b2v[c0 + 64 + j] + (&h1.x)[j];
            }
            *(float4*)(g_h1 + (size_t)node * H + c0)      = o0;
            *(float4*)(g_h1 + (size_t)node * H + c0 + 64) = o1;
        }
    }
}

// h2 = nodeMLP([mi, h1]);  xz = h2 @ in_proj_w ; split into g_x, g_z
__global__ __launch_bounds__(256, 3) void k_node2(
    const float* __restrict__ W1, const float* __restrict__ b1v,
    const float* __restrict__ W2, const float* __restrict__ b2v,
    const float* __restrict__ inpw, int Nn) {
    extern __shared__ char sraw[];
    SmemG& S = *(SmemG*)sraw;
    int tid = threadIdx.x;
    int row0 = blockIdx.x * 64;
    int tx = tid & 15, ty = tid >> 4;
    int c0 = tx * 4, r0 = ty * 4;
    int le = tid >> 2, lk = (tid & 3) * 8;
    int node_l = min(row0 + le, Nn - 1);
    ull acc[4][4] = {};
    for (int kc = 0; kc < 256; kc += 32) {
        const float* srcb = (kc < 128) ? g_mi : g_h1;
        const float* src = srcb + (size_t)node_l * H + (kc & 127) + lk;
        *(float4*)&S.At[le][lk]     = *(const float4*)src;
        *(float4*)&S.At[le][lk + 4] = *(const float4*)(src + 4);
        load_w_chunk(&S.Wt[0][0], W1 + kc * H, tid);
        __syncthreads();
        gemm_chunk(acc, &S.At[r0][0], &S.At[r0 + 1][0], &S.At[r0 + 2][0], &S.At[r0 + 3][0], &S.Wt[0][0], c0);
        __syncthreads();
    }
    #pragma unroll
    for (int i = 0; i < 4; i++) {
        float4 g0, g1;
        unpack_row(acc[i], g0, g1);
        float4 s0, s1;
        #pragma unroll
        for (int j = 0; j < 4; j++) {
            (&s0.x)[j] = silu((&g0.x)[j] + b1v[c0 + j]);
            (&s1.x)[j] = silu((&g1.x)[j] + b1v[c0 + 64 + j]);
        }
        *(float4*)&S.T1[r0 + i][c0]      = s0;
        *(float4*)&S.T1[r0 + i][c0 + 64] = s1;
        #pragma unroll
        for (int j = 0; j < 4; j++) acc[i][j] = 0ull;
    }
    __syncthreads();
    for (int kc = 0; kc < 128; kc += 32) {
        load_w_chunk(&S.Wt[0][0], W2 + kc * H, tid);
        __syncthreads();
        gemm_chunk(acc, &S.T1[r0][kc], &S.T1[r0 + 1][kc], &S.T1[r0 + 2][kc], &S.T1[r0 + 3][kc], &S.Wt[0][0], c0);
        __syncthreads();
    }
    float h2v[4][8];
    #pragma unroll
    for (int i = 0; i < 4; i++) {
        float4 g0, g1;
        unpack_row(acc[i], g0, g1);
        #pragma unroll
        for (int j = 0; j < 4; j++) {
            h2v[i][j]     = (&g0.x)[j] + b2v[c0 + j];
            h2v[i][4 + j] = (&g1.x)[j] + b2v[c0 + 64 + j];
        }
    }
    __syncthreads();
    #pragma unroll
    for (int i = 0; i < 4; i++) {
        *(float4*)&S.T1[r0 + i][c0]      = *(float4*)&h2v[i][0];
        *(float4*)&S.T1[r0 + i][c0 + 64] = *(float4*)&h2v[i][4];
    }
    __syncthreads();
    for (int half = 0; half < 2; half++) {
        #pragma unroll
        for (int i = 0; i < 4; i++)
            #pragma unroll
            for (int j = 0; j < 4; j++) acc[i][j] = 0ull;
        for (int kc = 0; kc < 128; kc += 32) {
            load_w_chunk_strided(&S.Wt[0][0], inpw + kc * 256 + half * 128, 256, tid);
            __syncthreads();
            gemm_chunk(acc, &S.T1[r0][kc], &S.T1[r0 + 1][kc], &S.T1[r0 + 2][kc], &S.T1[r0 + 3][kc], &S.Wt[0][0], c0);
            __syncthreads();
        }
        float* dst = half ? g_z : g_x;
        #pragma unroll
        for (int i = 0; i < 4; i++) {
            int node = row0 + r0 + i;
            if (node < Nn) {
                float4 g0, g1;
                unpack_row(acc[i], g0, g1);
                *(float4*)(dst + (size_t)node * H + c0)      = g0;
                *(float4*)(dst + (size_t)node * H + c0 + 64) = g1;
            }
        }
    }
}

// conv + silu -> xs ; B,C = xs @ x_proj_w[:,8:136] ; delta = softplus(xs @ M + dt_b)
__global__ __launch_bounds__(256, 3) void k_conv_proj(
    const float* __restrict__ xpw, const float* __restrict__ convw,
    const float* __restrict__ convb, const float* __restrict__ dtb, int Nn) {
    extern __shared__ char sraw[];
    SmemG& S = *(SmemG*)sraw;
    int tid = threadIdx.x;
    int row0 = blockIdx.x * 64;
    int tx = tid & 15, ty = tid >> 4;
    int c0 = tx * 4, r0 = ty * 4;
    for (int it = 0; it < 32; ++it) {
        int lin = it * 256 + tid;
        int r = lin >> 7, c = lin & 127;
        int node = row0 + r;
        float v = 0.f;
        if (node < Nn) {
            float a = convb[c];
            #pragma unroll
            for (int k = 0; k < 4; k++) {
                int t = node - 3 + k;
                if (t >= 0) a += convw[k * H + c] * g_x[(size_t)t * H + c];
            }
            v = silu(a);
            g_xs[(size_t)node * H + c] = v;
        }
        S.T1[r][c] = v;
    }
    __syncthreads();
    ull acc[4][4] = {};
    for (int kc = 0; kc < 128; kc += 32) {
        load_w_chunk_strided(&S.Wt[0][0], xpw + kc * 136 + 8, 136, tid);
        __syncthreads();
        gemm_chunk(acc, &S.T1[r0][kc], &S.T1[r0 + 1][kc], &S.T1[r0 + 2][kc], &S.T1[r0 + 3][kc], &S.Wt[0][0], c0);
        __syncthreads();
    }
    #pragma unroll
    for (int i = 0; i < 4; i++) {
        int node = row0 + r0 + i;
        if (node < Nn) {
            float4 g0, g1;
            unpack_row(acc[i], g0, g1);
            *(float4*)(g_Bm + (size_t)node * DS + c0) = g0;
            *(float4*)(g_Cm + (size_t)node * DS + c0) = g1;
        }
        #pragma unroll
        for (int j = 0; j < 4; j++) acc[i][j] = 0ull;
    }
    for (int kc = 0; kc < 128; kc += 32) {
        load_w_chunk(&S.Wt[0][0], g_M + kc * H, tid);
        __syncthreads();
        gemm_chunk(acc, &S.T1[r0][kc], &S.T1[r0 + 1][kc], &S.T1[r0 + 2][kc], &S.T1[r0 + 3][kc], &S.Wt[0][0], c0);
        __syncthreads();
    }
    #pragma unroll
    for (int i = 0; i < 4; i++) {
        int node = row0 + r0 + i;
        if (node < Nn) {
            float4 g0, g1;
            unpack_row(acc[i], g0, g1);
            float4 o0, o1;
            #pragma unroll
            for (int j = 0; j < 4; j++) {
                (&o0.x)[j] = softplus((&g0.x)[j] + dtb[c0 + j]);
                (&o1.x)[j] = softplus((&g1.x)[j] + dtb[c0 + 64 + j]);
            }
            *(float4*)(g_delta + (size_t)node * H + c0)      = o0;
            *(float4*)(g_delta + (size_t)node * H + c0 + 64) = o1;
        }
    }
}

// chunked selective scan, phase A
__global__ void k_scanA(const float* __restrict__ A_log, int Nn) {
    int warp = threadIdx.x >> 5;
    int lane = threadIdx.x & 31;
    int c = blockIdx.x;
    int hch = blockIdx.y * 8 + warp;
    int s0 = lane, s1 = lane + 32;
    float A0 = -__expf(A_log[hch * DS + s0]);
    float A1 = -__expf(A_log[hch * DS + s1]);
    float hc0 = 0.f, hc1 = 0.f, dsum = 0.f;
    int t0 = c * TCH, t1 = min(Nn, t0 + TCH);
    for (int t = t0; t < t1; ++t) {
        float d = __ldg(&g_delta[(size_t)t * H + hch]);
        float xv = __ldg(&g_xs[(size_t)t * H + hch]);
        float b0 = g_Bm[(size_t)t * DS + s0];
        float b1v = g_Bm[(size_t)t * DS + s1];
        float dx = d * xv;
        hc0 = __expf(d * A0) * hc0 + dx * b0;
        hc1 = __expf(d * A1) * hc1 + dx * b1v;
        dsum += d;
    }
    size_t o = ((size_t)c * H + hch) * DS;
    g_bstate[o + s0] = hc0;
    g_bstate[o + s1] = hc1;
    g_aprod[o + s0] = __expf(A0 * dsum);
    g_aprod[o + s1] = __expf(A1 * dsum);
}

// phase B
__global__ void k_prefix(int NC) {
    int hs = blockIdx.x * blockDim.x + threadIdx.x;
    float st = 0.f;
    for (int c = 0; c < NC; c++) {
        size_t o = (size_t)c * (H * DS) + hs;
        g_sstart[o] = st;
        st = g_aprod[o] * st + g_bstate[o];
    }
}

// phase C
__global__ void k_scanC(const float* __restrict__ A_log, const float* __restrict__ Dv, int Nn) {
    int warp = threadIdx.x >> 5;
    int lane = threadIdx.x & 31;
    int c = blockIdx.x;
    int hch = blockIdx.y * 8 + warp;
    int s0 = lane, s1 = lane + 32;
    float A0 = -__expf(A_log[hch * DS + s0]);
    float A1 = -__expf(A_log[hch * DS + s1]);
    size_t o = ((size_t)c * H + hch) * DS;
    float hc0 = g_sstart[o + s0];
    float hc1 = g_sstart[o + s1];
    float dh = Dv[hch];
    int t0 = c * TCH, t1 = min(Nn, t0 + TCH);
    for (int t = t0; t < t1; ++t) {
        float d = __ldg(&g_delta[(size_t)t * H + hch]);
        float xv = __ldg(&g_xs[(size_t)t * H + hch]);
        float b0 = g_Bm[(size_t)t * DS + s0];
        float b1v = g_Bm[(size_t)t * DS + s1];
        float c0 = g_Cm[(size_t)t * DS + s0];
        float c1 = g_Cm[(size_t)t * DS + s1];
        float dx = d * xv;
        hc0 = __expf(d * A0) * hc0 + dx * b0;
        hc1 = __expf(d * A1) * hc1 + dx * b1v;
        float p = hc0 * c0 + hc1 * c1;
        #pragma unroll
        for (int off = 16; off; off >>= 1) p += __shfl_down_sync(0xffffffffu, p, off);
        if (lane == 0) {
            float zv = g_z[(size_t)t * H + hch];
            g_y[(size_t)t * H + hch] = (p + dh * xv) * zv * sigm(zv);
        }
    }
}

// out = y @ out_proj_w
__global__ __launch_bounds__(256, 3) void k_out(const float* __restrict__ W, float* __restrict__ out, int Nn) {
    extern __shared__ char sraw[];
    SmemG& S = *(SmemG*)sraw;
    int tid = threadIdx.x;
    int row0 = blockIdx.x * 64;
    int tx = tid & 15, ty = tid >> 4;
    int c0 = tx * 4, r0 = ty * 4;
    for (int it = 0; it < 32; ++it) {
        int lin = it * 256 + tid;
        int r = lin >> 7, c = lin & 127;
        int node = min(row0 + r, Nn - 1);
        S.T1[r][c] = g_y[(size_t)node * H + c];
    }
    __syncthreads();
    ull acc[4][4] = {};
    for (int kc = 0; kc < 128; kc += 32) {
        load_w_chunk(&S.Wt[0][0], W + kc * H, tid);
        __syncthreads();
        gemm_chunk(acc, &S.T1[r0][kc], &S.T1[r0 + 1][kc], &S.T1[r0 + 2][kc], &S.T1[r0 + 3][kc], &S.Wt[0][0], c0);
        __syncthreads();
    }
    #pragma unroll
    for (int i = 0; i < 4; i++) {
        int node = row0 + r0 + i;
        if (node < Nn) {
            float4 g0, g1;
            unpack_row(acc[i], g0, g1);
            *(float4*)(out + (size_t)node * H + c0)      = g0;
            *(float4*)(out + (size_t)node * H + c0 + 64) = g1;
        }
    }
}

// ---------------- launch ----------------
extern "C" void kernel_launch(void* const* d_in, const int* in_sizes, int n_in,
                              void* d_out, int out_size) {
    const float* h      = (const float*)d_in[0];
    const void*  eidx   = d_in[1];
    const float* eattr  = (const float*)d_in[2];
    const float* e_w1   = (const float*)d_in[3];
    const float* e_b1   = (const float*)d_in[4];
    const float* e_w2   = (const float*)d_in[5];
    const float* e_b2   = (const float*)d_in[6];
    const float* inf_w  = (const float*)d_in[7];
    const float* inf_b  = (const float*)d_in[8];
    const float* n_w1   = (const float*)d_in[9];
    const float* n_b1   = (const float*)d_in[10];
    const float* n_w2   = (const float*)d_in[11];
    const float* n_b2   = (const float*)d_in[12];
    const float* in_prj = (const float*)d_in[13];
    const float* conv_w = (const float*)d_in[14];
    const float* conv_b = (const float*)d_in[15];
    const float* x_proj = (const float*)d_in[16];
    const float* dt_w   = (const float*)d_in[17];
    const float* dt_b   = (const float*)d_in[18];
    const float* A_log  = (const float*)d_in[19];
    const float* Dv     = (const float*)d_in[20];
    const float* out_w  = (const float*)d_in[21];

    int Nn = in_sizes[0] / H;
    int E  = in_sizes[2] / 2;
    int NC = (Nn + TCH - 1) / TCH;
    int nb = (Nn + 63) / 64;
    int ntiles = (E + ET - 1) / ET;
    int smemG = (int)sizeof(SmemG);

    cudaFuncSetAttribute(k_pq,        cudaFuncAttributeMaxDynamicSharedMemorySize, smemG);
    cudaFuncSetAttribute(k_node1,     cudaFuncAttributeMaxDynamicSharedMemorySize, smemG);
    cudaFuncSetAttribute(k_node2,     cudaFuncAttributeMaxDynamicSharedMemorySize, smemG);
    cudaFuncSetAttribute(k_conv_proj, cudaFuncAttributeMaxDynamicSharedMemorySize, smemG);
    cudaFuncSetAttribute(k_out,       cudaFuncAttributeMaxDynamicSharedMemorySize, smemG);

    // launch order puts k_edge_mma 4th -> it gets the ncu profile slot
    k_detect<<<1, 32>>>((const int*)eidx);
    k_premat<<<64, 256>>>(x_proj, dt_w);
    k_pq<<<nb, 256, smemG>>>(h, e_w1, Nn);
    int egrid = ntiles < 296 ? ntiles : 296;
    k_edge_mma<<<egrid, 256>>>(eidx, eattr, e_w1, e_b1, e_w2, e_b2, inf_w, inf_b, E, ntiles);
    // CSR build (independent of edge outputs; ordered after for profiling slot)
    k_zero_cnt<<<(Nn + 255) / 256, 256>>>(Nn);
    k_hist<<<(E + 255) / 256, 256>>>(eidx, E);
    k_scan_off<<<2, 1024>>>(Nn);
    k_fill<<<(E + 255) / 256, 256>>>(eidx, E);
    k_gather<<<(Nn + 7) / 8, 256>>>(Nn);
    // node + mamba pipeline
    k_node1<<<nb, 256, smemG>>>(h, n_w1, n_b1, n_w2, n_b2, Nn);
    k_node2<<<nb, 256, smemG>>>(n_w1, n_b1, n_w2, n_b2, in_prj, Nn);
    k_conv_proj<<<nb, 256, smemG>>>(x_proj, conv_w, conv_b, dt_b, Nn);
    dim3 gs(NC, 16);
    k_scanA<<<gs, 256>>>(A_log, Nn);
    k_prefix<<<32, 256>>>(NC);
    k_scanC<<<gs, 256>>>(A_log, Dv, Nn);
    k_out<<<nb, 256, smemG>>>(out_w, (float*)d_out, Nn);
}

// round 8
// speedup vs baseline: 1.2397x; 1.0604x over previous
#include <cuda_runtime.h>
#include <cuda_fp16.h>
#include <math.h>

#define H 128
#define DS 64
#define TCH 128
#define MAXN 20000
#define MAXNC 157

typedef unsigned long long ull;

// ---------------- scratch ----------------
__device__ float g_mi[MAXN * H];
__device__ float g_agg[MAXN * H];
__device__ float g_h1[MAXN * H];
__device__ float g_x[MAXN * H];
__device__ float g_z[MAXN * H];
__device__ float g_xs[MAXN * H];
__device__ float g_delta[MAXN * H];
__device__ float g_Bm[MAXN * DS];
__device__ float g_Cm[MAXN * DS];
__device__ float g_y[MAXN * H];
__device__ float g_P[MAXN * H];
__device__ float g_Q[MAXN * H];
__device__ float g_M[H * H];
__device__ float g_aprod[MAXNC * H * DS];
__device__ float g_bstate[MAXNC * H * DS];
__device__ float g_sstart[MAXNC * H * DS];
__device__ int   g_is64;

// ---------------- helpers ----------------
__device__ __forceinline__ float sigm(float v) { return 1.f / (1.f + __expf(-v)); }
__device__ __forceinline__ float silu(float v) { return v / (1.f + __expf(-v)); }
__device__ __forceinline__ float softplus(float v) { return (v > 20.f) ? v : log1pf(__expf(v)); }

__device__ __forceinline__ ull pk2(float a, float b) {
    ull r; asm("mov.b64 %0, {%1,%2};" : "=l"(r) : "f"(a), "f"(b)); return r;
}
__device__ __forceinline__ void upk2(ull v, float& a, float& b) {
    asm("mov.b64 {%0,%1}, %2;" : "=f"(a), "=f"(b) : "l"(v));
}
__device__ __forceinline__ void fma2(ull& d, ull a, ull b) {
    asm("fma.rn.f32x2 %0, %1, %2, %0;" : "+l"(d) : "l"(a), "l"(b));
}
__device__ __forceinline__ void red2(float* p, float a, float b) {
    asm volatile("red.global.add.v2.f32 [%0], {%1,%2};"
                 :: "l"(p), "f"(a), "f"(b) : "memory");
}
__device__ __forceinline__ unsigned smem_u32(const void* p) {
    unsigned r;
    asm("{ .reg .u64 t; cvta.to.shared.u64 t, %1; cvt.u32.u64 %0, t; }" : "=r"(r) : "l"(p));
    return r;
}
// fp16 m16n8k16 MMA (fp32 accum)
__device__ __forceinline__ void mma16(float* d, unsigned a0, unsigned a1, unsigned a2, unsigned a3,
                                      unsigned b0, unsigned b1) {
    asm volatile(
        "mma.sync.aligned.m16n8k16.row.col.f32.f16.f16.f32 "
        "{%0,%1,%2,%3}, {%4,%5,%6,%7}, {%8,%9}, {%0,%1,%2,%3};"
        : "+f"(d[0]), "+f"(d[1]), "+f"(d[2]), "+f"(d[3])
        : "r"(a0), "r"(a1), "r"(a2), "r"(a3), "r"(b0), "r"(b1));
}
__device__ __forceinline__ void ldmx4(unsigned* a, unsigned addr) {
    asm volatile("ldmatrix.sync.aligned.m8n8.x4.shared.b16 {%0,%1,%2,%3}, [%4];"
                 : "=r"(a[0]), "=r"(a[1]), "=r"(a[2]), "=r"(a[3]) : "r"(addr));
}
__device__ __forceinline__ unsigned h2pack(float a, float b) {
    __half2 h = __floats2half2_rn(a, b);
    return *(unsigned*)&h;
}

// ---------------- generic SIMT GEMM infra ----------------
struct SmemG {
    float At[64][36];
    float Wt[32][128];
    float T1[64][132];
};

__device__ __forceinline__ void load_w_chunk(float* wt, const float* __restrict__ src, int tid) {
    #pragma unroll
    for (int j = 0; j < 4; j++) {
        int li = j * 1024 + tid * 4;
        *(float4*)&wt[li] = *(const float4*)(src + li);
    }
}
__device__ __forceinline__ void load_w_chunk_strided(float* wt, const float* __restrict__ base, int ldg, int tid) {
    #pragma unroll
    for (int j = 0; j < 4; j++) {
        int li = j * 1024 + tid * 4;
        int row = li >> 7, col = li & 127;
        *(float4*)&wt[li] = *(const float4*)(base + row * ldg + col);
    }
}

__device__ __forceinline__ void gemm_chunk(ull (&acc)[4][4],
                                           const float* a0, const float* a1,
                                           const float* a2, const float* a3,
                                           const float* wt, int c0) {
    #pragma unroll
    for (int kk = 0; kk < 32; kk += 4) {
        float4 A0 = *(const float4*)(a0 + kk);
        float4 A1 = *(const float4*)(a1 + kk);
        float4 A2 = *(const float4*)(a2 + kk);
        float4 A3 = *(const float4*)(a3 + kk);
        const float* w = wt + kk * 128 + c0;
        #pragma unroll
        for (int k4 = 0; k4 < 4; k4++) {
            ulonglong2 bA = *(const ulonglong2*)(w + k4 * 128);
            ulonglong2 bB = *(const ulonglong2*)(w + k4 * 128 + 64);
            float fa0 = (&A0.x)[k4], fa1 = (&A1.x)[k4];
            float fa2 = (&A2.x)[k4], fa3 = (&A3.x)[k4];
            ull p0 = pk2(fa0, fa0), p1 = pk2(fa1, fa1);
            ull p2 = pk2(fa2, fa2), p3 = pk2(fa3, fa3);
            fma2(acc[0][0], p0, bA.x); fma2(acc[0][1], p0, bA.y); fma2(acc[0][2], p0, bB.x); fma2(acc[0][3], p0, bB.y);
            fma2(acc[1][0], p1, bA.x); fma2(acc[1][1], p1, bA.y); fma2(acc[1][2], p1, bB.x); fma2(acc[1][3], p1, bB.y);
            fma2(acc[2][0], p2, bA.x); fma2(acc[2][1], p2, bA.y); fma2(acc[2][2], p2, bB.x); fma2(acc[2][3], p2, bB.y);
            fma2(acc[3][0], p3, bA.x); fma2(acc[3][1], p3, bA.y); fma2(acc[3][2], p3, bB.x); fma2(acc[3][3], p3, bB.y);
        }
    }
}
__device__ __forceinline__ void unpack_row(const ull* accr, float4& g0, float4& g1) {
    upk2(accr[0], g0.x, g0.y);
    upk2(accr[1], g0.z, g0.w);
    upk2(accr[2], g1.x, g1.y);
    upk2(accr[3], g1.z, g1.w);
}

// ---------------- kernels ----------------
__global__ void k_detect(const int* __restrict__ p) {
    if (threadIdx.x == 0) {
        int nz = 0;
        for (int i = 1; i < 128; i += 2) nz += (p[i] != 0);
        g_is64 = (nz == 0) ? 1 : 0;
    }
}

__global__ void k_zero(int n) {
    for (int i = blockIdx.x * blockDim.x + threadIdx.x; i < n; i += gridDim.x * blockDim.x) {
        g_mi[i] = 0.f;
        g_agg[i] = 0.f;
    }
}

__global__ void k_premat(const float* __restrict__ xpw, const float* __restrict__ dtw) {
    int o = blockIdx.x * blockDim.x + threadIdx.x;
    int i = o >> 7, j = o & 127;
    float s = 0.f;
    #pragma unroll
    for (int r = 0; r < 8; r++) s += xpw[i * 136 + r] * dtw[r * 128 + j];
    g_M[o] = s;
}

// P = h @ W1[0:128], Q = h @ W1[128:256]
__global__ __launch_bounds__(256, 3) void k_pq(
    const float* __restrict__ h, const float* __restrict__ W1, int Nn) {
    extern __shared__ char sraw[];
    SmemG& S = *(SmemG*)sraw;
    int tid = threadIdx.x;
    int row0 = blockIdx.x * 64;
    int tx = tid & 15, ty = tid >> 4;
    int c0 = tx * 4, r0 = ty * 4;
    for (int it = 0; it < 32; ++it) {
        int lin = it * 256 + tid;
        int r = lin >> 7, c = lin & 127;
        int node = min(row0 + r, Nn - 1);
        S.T1[r][c] = h[(size_t)node * H + c];
    }
    __syncthreads();
    for (int tgt = 0; tgt < 2; tgt++) {
        ull acc[4][4] = {};
        for (int kc = 0; kc < 128; kc += 32) {
            load_w_chunk(&S.Wt[0][0], W1 + (tgt * 128 + kc) * H, tid);
            __syncthreads();
            gemm_chunk(acc, &S.T1[r0][kc], &S.T1[r0 + 1][kc], &S.T1[r0 + 2][kc], &S.T1[r0 + 3][kc], &S.Wt[0][0], c0);
            __syncthreads();
        }
        float* dst = tgt ? g_Q : g_P;
        #pragma unroll
        for (int i = 0; i < 4; i++) {
            int node = row0 + r0 + i;
            if (node < Nn) {
                float4 g0, g1;
                unpack_row(acc[i], g0, g1);
                *(float4*)(dst + (size_t)node * H + c0)      = g0;
                *(float4*)(dst + (size_t)node * H + c0 + 64) = g1;
            }
        }
    }
}

// -------- edge kernel: stage-2 via fp16 ldmatrix mma.sync m16n8k16 + red2 scatter --------
#define ET 32
#define APITCH 136   // halves per row: 272B, conflict-free for ldmatrix

struct SmemE {
    __half As[ET][APITCH];
    int   rs[ET];
    int   cs[ET];
    float ea0[ET], ea1[ET];
    float wc0[H], wc1[H], b1s[H], b2s[H], infs[H];
    float dot[ET];
    float gg[ET];
};

__global__ __launch_bounds__(256, 2) void k_edge_mma(
    const void* __restrict__ eidx, const float* __restrict__ eattr,
    const float* __restrict__ W1, const float* __restrict__ b1,
    const float* __restrict__ W2, const float* __restrict__ b2,
    const float* __restrict__ infw, const float* __restrict__ infb,
    int E, int ntiles) {
    __shared__ SmemE S;
    int tid = threadIdx.x;
    int lane = tid & 31, wid = tid >> 5;
    int gid = lane >> 2, tig = lane & 3;
    int is64 = g_is64;

    if (tid < H) {
        S.wc0[tid]  = W1[256 * H + tid];
        S.wc1[tid]  = W1[257 * H + tid];
        S.b1s[tid]  = b1[tid];
        S.b2s[tid]  = b2[tid];
        S.infs[tid] = infw[tid];
    }
    float infb0 = infb[0];

    // preload W2^T fragments, fp16: warp's 16-col N-slice. 8 k16-steps.
    int nb = wid * 16;
    unsigned bf[8][2][2];
    #pragma unroll
    for (int ks = 0; ks < 8; ks++) {
        #pragma unroll
        for (int nt = 0; nt < 2; nt++) {
            int k0 = ks * 16 + 2 * tig;
            int n = nb + nt * 8 + gid;
            bf[ks][nt][0] = h2pack(W2[k0 * H + n],       W2[(k0 + 1) * H + n]);
            bf[ks][nt][1] = h2pack(W2[(k0 + 8) * H + n], W2[(k0 + 9) * H + n]);
        }
    }
    __syncthreads();

    int gr = tid >> 3, gc = (tid & 7) * 16;
    unsigned as_base = smem_u32(&S.As[0][0]);
    // per-thread ldmatrix address components (row/col within 16x16 tile block)
    int lrow = (lane & 7) + ((lane >> 3) & 1) * 8;
    int lcolh = (lane >> 4) * 8;

    for (int tile = blockIdx.x; tile < ntiles; tile += gridDim.x) {
        int t0 = tile * ET;
        if (tid < ET) {
            int e = min(t0 + tid, E - 1);
            int r, c;
            if (is64) {
                const long long* q = (const long long*)eidx;
                r = (int)q[e]; c = (int)q[(size_t)E + e];
            } else {
                const int* q = (const int*)eidx;
                r = q[e]; c = q[E + e];
            }
            S.rs[tid] = r; S.cs[tid] = c;
            S.ea0[tid] = eattr[2 * e];
            S.ea1[tid] = eattr[2 * e + 1];
            S.dot[tid] = 0.f;
        }
        __syncthreads();

        // gather: 8 threads/row, 16 cols each; fp32 math, fp16 store (2x 16B STS)
        {
            const float* Pr = g_P + (size_t)S.rs[gr] * H;
            const float* Qr = g_Q + (size_t)S.cs[gr] * H;
            float e0 = S.ea0[gr], e1 = S.ea1[gr];
            unsigned hv[8];
            #pragma unroll
            for (int j = 0; j < 4; j++) {
                int c = gc + j * 4;
                float4 pv = *(const float4*)(Pr + c);
                float4 qv = *(const float4*)(Qr + c);
                float4 w0 = *(const float4*)&S.wc0[c];
                float4 w1 = *(const float4*)&S.wc1[c];
                float4 bb = *(const float4*)&S.b1s[c];
                float o[4];
                #pragma unroll
                for (int jj = 0; jj < 4; jj++) {
                    float v = (&pv.x)[jj] + (&qv.x)[jj]
                            + e0 * (&w0.x)[jj] + e1 * (&w1.x)[jj] + (&bb.x)[jj];
                    o[jj] = silu(v);
                }
                hv[j * 2]     = h2pack(o[0], o[1]);
                hv[j * 2 + 1] = h2pack(o[2], o[3]);
            }
            *(uint4*)&S.As[gr][gc]     = *(uint4*)&hv[0];
            *(uint4*)&S.As[gr][gc + 8] = *(uint4*)&hv[4];
        }
        __syncthreads();

        // MMA: warp computes 32 rows x its 16 cols; 2 mg x 8 ks, A via ldmatrix.x4
        float acc[2][2][4];
        #pragma unroll
        for (int mg = 0; mg < 2; mg++)
            #pragma unroll
            for (int nt = 0; nt < 2; nt++)
                #pragma unroll
                for (int j = 0; j < 4; j++) acc[mg][nt][j] = 0.f;
        #pragma unroll
        for (int mg = 0; mg < 2; mg++) {
            unsigned rowbase = as_base + ((mg * 16 + lrow) * APITCH + lcolh) * 2;
            #pragma unroll
            for (int ks = 0; ks < 8; ks++) {
                unsigned a[4];
                ldmx4(a, rowbase + ks * 32);
                mma16(acc[mg][0], a[0], a[1], a[2], a[3], bf[ks][0][0], bf[ks][0][1]);
                mma16(acc[mg][1], a[0], a[1], a[2], a[3], bf[ks][1][0], bf[ks][1][1]);
            }
        }

        // inf-gate dot partials (quad-reduce, then smem atomic)
        #pragma unroll
        for (int mg = 0; mg < 2; mg++) {
            int r0 = mg * 16 + gid, r1 = r0 + 8;
            float p0 = 0.f, p1 = 0.f;
            #pragma unroll
            for (int nt = 0; nt < 2; nt++) {
                int c = nb + nt * 8 + 2 * tig;
                float i0 = S.infs[c], i1 = S.infs[c + 1];
                float v0 = silu(acc[mg][nt][0] + S.b2s[c]);
                float v1 = silu(acc[mg][nt][1] + S.b2s[c + 1]);
                float v2 = silu(acc[mg][nt][2] + S.b2s[c]);
                float v3 = silu(acc[mg][nt][3] + S.b2s[c + 1]);
                p0 += v0 * i0 + v1 * i1;
                p1 += v2 * i0 + v3 * i1;
            }
            p0 += __shfl_xor_sync(0xffffffffu, p0, 1, 4);
            p0 += __shfl_xor_sync(0xffffffffu, p0, 2, 4);
            p1 += __shfl_xor_sync(0xffffffffu, p1, 1, 4);
            p1 += __shfl_xor_sync(0xffffffffu, p1, 2, 4);
            if (tig == 0) {
                atomicAdd(&S.dot[r0], p0);
                atomicAdd(&S.dot[r1], p1);
            }
        }
        __syncthreads();
        if (tid < ET) S.gg[tid] = sigm(S.dot[tid] + infb0);
        __syncthreads();

        // scatter (red2 atomics, overlapped with next tile's work across CTAs)
        #pragma unroll
        for (int mg = 0; mg < 2; mg++) {
            int r0 = mg * 16 + gid, r1 = r0 + 8;
            #pragma unroll
            for (int nt = 0; nt < 2; nt++) {
                int c = nb + nt * 8 + 2 * tig;
                float v0 = silu(acc[mg][nt][0] + S.b2s[c]);
                float v1 = silu(acc[mg][nt][1] + S.b2s[c + 1]);
                float v2 = silu(acc[mg][nt][2] + S.b2s[c]);
                float v3 = silu(acc[mg][nt][3] + S.b2s[c + 1]);
                if (t0 + r0 < E) {
                    float g = S.gg[r0];
                    red2(g_agg + (size_t)S.rs[r0] * H + c, v0, v1);
                    red2(g_mi + (size_t)S.cs[r0] * H + c, v0 * g, v1 * g);
                }
                if (t0 + r1 < E) {
                    float g = S.gg[r1];
                    red2(g_agg + (size_t)S.rs[r1] * H + c, v2, v3);
                    red2(g_mi + (size_t)S.cs[r1] * H + c, v2 * g, v3 * g);
                }
            }
        }
        __syncthreads();
    }
}

// h1 = h + nodeMLP([h, agg])
__global__ __launch_bounds__(256, 3) void k_node1(
    const float* __restrict__ h,
    const float* __restrict__ W1, const float* __restrict__ b1v,
    const float* __restrict__ W2, const float* __restrict__ b2v, int Nn) {
    extern __shared__ char sraw[];
    SmemG& S = *(SmemG*)sraw;
    int tid = threadIdx.x;
    int row0 = blockIdx.x * 64;
    int tx = tid & 15, ty = tid >> 4;
    int c0 = tx * 4, r0 = ty * 4;
    int le = tid >> 2, lk = (tid & 3) * 8;
    int node_l = min(row0 + le, Nn - 1);
    ull acc[4][4] = {};
    for (int kc = 0; kc < 256; kc += 32) {
        const float* srcb = (kc < 128) ? h : g_agg;
        const float* src = srcb + (size_t)node_l * H + (kc & 127) + lk;
        *(float4*)&S.At[le][lk]     = *(const float4*)src;
        *(float4*)&S.At[le][lk + 4] = *(const float4*)(src + 4);
        load_w_chunk(&S.Wt[0][0], W1 + kc * H, tid);
        __syncthreads();
        gemm_chunk(acc, &S.At[r0][0], &S.At[r0 + 1][0], &S.At[r0 + 2][0], &S.At[r0 + 3][0], &S.Wt[0][0], c0);
        __syncthreads();
    }
    #pragma unroll
    for (int i = 0; i < 4; i++) {
        float4 g0, g1;
        unpack_row(acc[i], g0, g1);
        float4 s0, s1;
        #pragma unroll
        for (int j = 0; j < 4; j++) {
            (&s0.x)[j] = silu((&g0.x)[j] + b1v[c0 + j]);
            (&s1.x)[j] = silu((&g1.x)[j] + b1v[c0 + 64 + j]);
        }
        *(float4*)&S.T1[r0 + i][c0]      = s0;
        *(float4*)&S.T1[r0 + i][c0 + 64] = s1;
        #pragma unroll
        for (int j = 0; j < 4; j++) acc[i][j] = 0ull;
    }
    __syncthreads();
    for (int kc = 0; kc < 128; kc += 32) {
        load_w_chunk(&S.Wt[0][0], W2 + kc * H, tid);
        __syncthreads();
        gemm_chunk(acc, &S.T1[r0][kc], &S.T1[r0 + 1][kc], &S.T1[r0 + 2][kc], &S.T1[r0 + 3][kc], &S.Wt[0][0], c0);
        __syncthreads();
    }
    #pragma unroll
    for (int i = 0; i < 4; i++) {
        int node = row0 + r0 + i;
        if (node < Nn) {
            float4 g0, g1;
            unpack_row(acc[i], g0, g1);
            const float* hr = h + (size_t)node * H;
            float4 h0 = *(const float4*)(hr + c0);
            float4 h1 = *(const float4*)(hr + c0 + 64);
            float4 o0, o1;
            #pragma unroll
            for (int j = 0; j < 4; j++) {
                (&o0.x)[j] = (&g0.x)[j] + b2v[c0 + j]      + (&h0.x)[j];
                (&o1.x)[j] = (&g1.x)[j] + b2v[c0 + 64 + j] + (&h1.x)[j];
            }
            *(float4*)(g_h1 + (size_t)node * H + c0)      = o0;
            *(float4*)(g_h1 + (size_t)node * H + c0 + 64) = o1;
        }
    }
}

// h2 = nodeMLP([mi, h1]);  xz = h2 @ in_proj_w ; split into g_x, g_z
__global__ __launch_bounds__(256, 3) void k_node2(
    const float* __restrict__ W1, const float* __restrict__ b1v,
    const float* __restrict__ W2, const float* __restrict__ b2v,
    const float* __restrict__ inpw, int Nn) {
    extern __shared__ char sraw[];
    SmemG& S = *(SmemG*)sraw;
    int tid = threadIdx.x;
    int row0 = blockIdx.x * 64;
    int tx = tid & 15, ty = tid >> 4;
    int c0 = tx * 4, r0 = ty * 4;
    int le = tid >> 2, lk = (tid & 3) * 8;
    int node_l = min(row0 + le, Nn - 1);
    ull acc[4][4] = {};
    for (int kc = 0; kc < 256; kc += 32) {
        const float* srcb = (kc < 128) ? g_mi : g_h1;
        const float* src = srcb + (size_t)node_l * H + (kc & 127) + lk;
        *(float4*)&S.At[le][lk]     = *(const float4*)src;
        *(float4*)&S.At[le][lk + 4] = *(const float4*)(src + 4);
        load_w_chunk(&S.Wt[0][0], W1 + kc * H, tid);
        __syncthreads();
        gemm_chunk(acc, &S.At[r0][0], &S.At[r0 + 1][0], &S.At[r0 + 2][0], &S.At[r0 + 3][0], &S.Wt[0][0], c0);
        __syncthreads();
    }
    #pragma unroll
    for (int i = 0; i < 4; i++) {
        float4 g0, g1;
        unpack_row(acc[i], g0, g1);
        float4 s0, s1;
        #pragma unroll
        for (int j = 0; j < 4; j++) {
            (&s0.x)[j] = silu((&g0.x)[j] + b1v[c0 + j]);
            (&s1.x)[j] = silu((&g1.x)[j] + b1v[c0 + 64 + j]);
        }
        *(float4*)&S.T1[r0 + i][c0]      = s0;
        *(float4*)&S.T1[r0 + i][c0 + 64] = s1;
        #pragma unroll
        for (int j = 0; j < 4; j++) acc[i][j] = 0ull;
    }
    __syncthreads();
    for (int kc = 0; kc < 128; kc += 32) {
        load_w_chunk(&S.Wt[0][0], W2 + kc * H, tid);
        __syncthreads();
        gemm_chunk(acc, &S.T1[r0][kc], &S.T1[r0 + 1][kc], &S.T1[r0 + 2][kc], &S.T1[r0 + 3][kc], &S.Wt[0][0], c0);
        __syncthreads();
    }
    float h2v[4][8];
    #pragma unroll
    for (int i = 0; i < 4; i++) {
        float4 g0, g1;
        unpack_row(acc[i], g0, g1);
        #pragma unroll
        for (int j = 0; j < 4; j++) {
            h2v[i][j]     = (&g0.x)[j] + b2v[c0 + j];
            h2v[i][4 + j] = (&g1.x)[j] + b2v[c0 + 64 + j];
        }
    }
    __syncthreads();
    #pragma unroll
    for (int i = 0; i < 4; i++) {
        *(float4*)&S.T1[r0 + i][c0]      = *(float4*)&h2v[i][0];
        *(float4*)&S.T1[r0 + i][c0 + 64] = *(float4*)&h2v[i][4];
    }
    __syncthreads();
    for (int half = 0; half < 2; half++) {
        #pragma unroll
        for (int i = 0; i < 4; i++)
            #pragma unroll
            for (int j = 0; j < 4; j++) acc[i][j] = 0ull;
        for (int kc = 0; kc < 128; kc += 32) {
            load_w_chunk_strided(&S.Wt[0][0], inpw + kc * 256 + half * 128, 256, tid);
            __syncthreads();
            gemm_chunk(acc, &S.T1[r0][kc], &S.T1[r0 + 1][kc], &S.T1[r0 + 2][kc], &S.T1[r0 + 3][kc], &S.Wt[0][0], c0);
            __syncthreads();
        }
        float* dst = half ? g_z : g_x;
        #pragma unroll
        for (int i = 0; i < 4; i++) {
            int node = row0 + r0 + i;
            if (node < Nn) {
                float4 g0, g1;
                unpack_row(acc[i], g0, g1);
                *(float4*)(dst + (size_t)node * H + c0)      = g0;
                *(float4*)(dst + (size_t)node * H + c0 + 64) = g1;
            }
        }
    }
}

// conv + silu -> xs ; B,C = xs @ x_proj_w[:,8:136] ; delta = softplus(xs @ M + dt_b)
__global__ __launch_bounds__(256, 3) void k_conv_proj(
    const float* __restrict__ xpw, const float* __restrict__ convw,
    const float* __restrict__ convb, const float* __restrict__ dtb, int Nn) {
    extern __shared__ char sraw[];
    SmemG& S = *(SmemG*)sraw;
    int tid = threadIdx.x;
    int row0 = blockIdx.x * 64;
    int tx = tid & 15, ty = tid >> 4;
    int c0 = tx * 4, r0 = ty * 4;
    for (int it = 0; it < 32; ++it) {
        int lin = it * 256 + tid;
        int r = lin >> 7, c = lin & 127;
        int node = row0 + r;
        float v = 0.f;
        if (node < Nn) {
            float a = convb[c];
            #pragma unroll
            for (int k = 0; k < 4; k++) {
                int t = node - 3 + k;
                if (t >= 0) a += convw[k * H + c] * g_x[(size_t)t * H + c];
            }
            v = silu(a);
            g_xs[(size_t)node * H + c] = v;
        }
        S.T1[r][c] = v;
    }
    __syncthreads();
    ull acc[4][4] = {};
    for (int kc = 0; kc < 128; kc += 32) {
        load_w_chunk_strided(&S.Wt[0][0], xpw + kc * 136 + 8, 136, tid);
        __syncthreads();
        gemm_chunk(acc, &S.T1[r0][kc], &S.T1[r0 + 1][kc], &S.T1[r0 + 2][kc], &S.T1[r0 + 3][kc], &S.Wt[0][0], c0);
        __syncthreads();
    }
    #pragma unroll
    for (int i = 0; i < 4; i++) {
        int node = row0 + r0 + i;
        if (node < Nn) {
            float4 g0, g1;
            unpack_row(acc[i], g0, g1);
            *(float4*)(g_Bm + (size_t)node * DS + c0) = g0;
            *(float4*)(g_Cm + (size_t)node * DS + c0) = g1;
        }
        #pragma unroll
        for (int j = 0; j < 4; j++) acc[i][j] = 0ull;
    }
    for (int kc = 0; kc < 128; kc += 32) {
        load_w_chunk(&S.Wt[0][0], g_M + kc * H, tid);
        __syncthreads();
        gemm_chunk(acc, &S.T1[r0][kc], &S.T1[r0 + 1][kc], &S.T1[r0 + 2][kc], &S.T1[r0 + 3][kc], &S.Wt[0][0], c0);
        __syncthreads();
    }
    #pragma unroll
    for (int i = 0; i < 4; i++) {
        int node = row0 + r0 + i;
        if (node < Nn) {
            float4 g0, g1;
            unpack_row(acc[i], g0, g1);
            float4 o0, o1;
            #pragma unroll
            for (int j = 0; j < 4; j++) {
                (&o0.x)[j] = softplus((&g0.x)[j] + dtb[c0 + j]);
                (&o1.x)[j] = softplus((&g1.x)[j] + dtb[c0 + 64 + j]);
            }
            *(float4*)(g_delta + (size_t)node * H + c0)      = o0;
            *(float4*)(g_delta + (size_t)node * H + c0 + 64) = o1;
        }
    }
}

// chunked selective scan, phase A
__global__ void k_scanA(const float* __restrict__ A_log, int Nn) {
    int warp = threadIdx.x >> 5;
    int lane = threadIdx.x & 31;
    int c = blockIdx.x;
    int hch = blockIdx.y * 8 + warp;
    int s0 = lane, s1 = lane + 32;
    float A0 = -__expf(A_log[hch * DS + s0]);
    float A1 = -__expf(A_log[hch * DS + s1]);
    float hc0 = 0.f, hc1 = 0.f, dsum = 0.f;
    int t0 = c * TCH, t1 = min(Nn, t0 + TCH);
    for (int t = t0; t < t1; ++t) {
        float d = __ldg(&g_delta[(size_t)t * H + hch]);
        float xv = __ldg(&g_xs[(size_t)t * H + hch]);
        float b0 = g_Bm[(size_t)t * DS + s0];
        float b1v = g_Bm[(size_t)t * DS + s1];
        float dx = d * xv;
        hc0 = __expf(d * A0) * hc0 + dx * b0;
        hc1 = __expf(d * A1) * hc1 + dx * b1v;
        dsum += d;
    }
    size_t o = ((size_t)c * H + hch) * DS;
    g_bstate[o + s0] = hc0;
    g_bstate[o + s1] = hc1;
    g_aprod[o + s0] = __expf(A0 * dsum);
    g_aprod[o + s1] = __expf(A1 * dsum);
}

// phase B
__global__ void k_prefix(int NC) {
    int hs = blockIdx.x * blockDim.x + threadIdx.x;
    float st = 0.f;
    for (int c = 0; c < NC; c++) {
        size_t o = (size_t)c * (H * DS) + hs;
        g_sstart[o] = st;
        st = g_aprod[o] * st + g_bstate[o];
    }
}

// phase C
__global__ void k_scanC(const float* __restrict__ A_log, const float* __restrict__ Dv, int Nn) {
    int warp = threadIdx.x >> 5;
    int lane = threadIdx.x & 31;
    int c = blockIdx.x;
    int hch = blockIdx.y * 8 + warp;
    int s0 = lane, s1 = lane + 32;
    float A0 = -__expf(A_log[hch * DS + s0]);
    float A1 = -__expf(A_log[hch * DS + s1]);
    size_t o = ((size_t)c * H + hch) * DS;
    float hc0 = g_sstart[o + s0];
    float hc1 = g_sstart[o + s1];
    float dh = Dv[hch];
    int t0 = c * TCH, t1 = min(Nn, t0 + TCH);
    for (int t = t0; t < t1; ++t) {
        float d = __ldg(&g_delta[(size_t)t * H + hch]);
        float xv = __ldg(&g_xs[(size_t)t * H + hch]);
        float b0 = g_Bm[(size_t)t * DS + s0];
        float b1v = g_Bm[(size_t)t * DS + s1];
        float c0 = g_Cm[(size_t)t * DS + s0];
        float c1 = g_Cm[(size_t)t * DS + s1];
        float dx = d * xv;
        hc0 = __expf(d * A0) * hc0 + dx * b0;
        hc1 = __expf(d * A1) * hc1 + dx * b1v;
        float p = hc0 * c0 + hc1 * c1;
        #pragma unroll
        for (int off = 16; off; off >>= 1) p += __shfl_down_sync(0xffffffffu, p, off);
        if (lane == 0) {
            float zv = g_z[(size_t)t * H + hch];
            g_y[(size_t)t * H + hch] = (p + dh * xv) * zv * sigm(zv);
        }
    }
}

// out = y @ out_proj_w
__global__ __launch_bounds__(256, 3) void k_out(const float* __restrict__ W, float* __restrict__ out, int Nn) {
    extern __shared__ char sraw[];
    SmemG& S = *(SmemG*)sraw;
    int tid = threadIdx.x;
    int row0 = blockIdx.x * 64;
    int tx = tid & 15, ty = tid >> 4;
    int c0 = tx * 4, r0 = ty * 4;
    for (int it = 0; it < 32; ++it) {
        int lin = it * 256 + tid;
        int r = lin >> 7, c = lin & 127;
        int node = min(row0 + r, Nn - 1);
        S.T1[r][c] = g_y[(size_t)node * H + c];
    }
    __syncthreads();
    ull acc[4][4] = {};
    for (int kc = 0; kc < 128; kc += 32) {
        load_w_chunk(&S.Wt[0][0], W + kc * H, tid);
        __syncthreads();
        gemm_chunk(acc, &S.T1[r0][kc], &S.T1[r0 + 1][kc], &S.T1[r0 + 2][kc], &S.T1[r0 + 3][kc], &S.Wt[0][0], c0);
        __syncthreads();
    }
    #pragma unroll
    for (int i = 0; i < 4; i++) {
        int node = row0 + r0 + i;
        if (node < Nn) {
            float4 g0, g1;
            unpack_row(acc[i], g0, g1);
            *(float4*)(out + (size_t)node * H + c0)      = g0;
            *(float4*)(out + (size_t)node * H + c0 + 64) = g1;
        }
    }
}

// ---------------- launch ----------------
extern "C" void kernel_launch(void* const* d_in, const int* in_sizes, int n_in,
                              void* d_out, int out_size) {
    const float* h      = (const float*)d_in[0];
    const void*  eidx   = d_in[1];
    const float* eattr  = (const float*)d_in[2];
    const float* e_w1   = (const float*)d_in[3];
    const float* e_b1   = (const float*)d_in[4];
    const float* e_w2   = (const float*)d_in[5];
    const float* e_b2   = (const float*)d_in[6];
    const float* inf_w  = (const float*)d_in[7];
    const float* inf_b  = (const float*)d_in[8];
    const float* n_w1   = (const float*)d_in[9];
    const float* n_b1   = (const float*)d_in[10];
    const float* n_w2   = (const float*)d_in[11];
    const float* n_b2   = (const float*)d_in[12];
    const float* in_prj = (const float*)d_in[13];
    const float* conv_w = (const float*)d_in[14];
    const float* conv_b = (const float*)d_in[15];
    const float* x_proj = (const float*)d_in[16];
    const float* dt_w   = (const float*)d_in[17];
    const float* dt_b   = (const float*)d_in[18];
    const float* A_log  = (const float*)d_in[19];
    const float* Dv     = (const float*)d_in[20];
    const float* out_w  = (const float*)d_in[21];

    int Nn = in_sizes[0] / H;
    int E  = in_sizes[2] / 2;
    int NC = (Nn + TCH - 1) / TCH;
    int nb = (Nn + 63) / 64;
    int ntiles = (E + ET - 1) / ET;
    int smemG = (int)sizeof(SmemG);

    cudaFuncSetAttribute(k_pq,        cudaFuncAttributeMaxDynamicSharedMemorySize, smemG);
    cudaFuncSetAttribute(k_node1,     cudaFuncAttributeMaxDynamicSharedMemorySize, smemG);
    cudaFuncSetAttribute(k_node2,     cudaFuncAttributeMaxDynamicSharedMemorySize, smemG);
    cudaFuncSetAttribute(k_conv_proj, cudaFuncAttributeMaxDynamicSharedMemorySize, smemG);
    cudaFuncSetAttribute(k_out,       cudaFuncAttributeMaxDynamicSharedMemorySize, smemG);

    // k_edge_mma in the 4th (profiled) launch slot
    k_detect<<<1, 32>>>((const int*)eidx);
    k_zero<<<256, 256>>>(Nn * H);
    k_pq<<<nb, 256, smemG>>>(h, e_w1, Nn);
    int egrid = ntiles < 296 ? ntiles : 296;
    k_edge_mma<<<egrid, 256>>>(eidx, eattr, e_w1, e_b1, e_w2, e_b2, inf_w, inf_b, E, ntiles);
    k_premat<<<64, 256>>>(x_proj, dt_w);
    k_node1<<<nb, 256, smemG>>>(h, n_w1, n_b1, n_w2, n_b2, Nn);
    k_node2<<<nb, 256, smemG>>>(n_w1, n_b1, n_w2, n_b2, in_prj, Nn);
    k_conv_proj<<<nb, 256, smemG>>>(x_proj, conv_w, conv_b, dt_b, Nn);
    dim3 gs(NC, 16);
    k_scanA<<<gs, 256>>>(A_log, Nn);
    k_prefix<<<32, 256>>>(NC);
    k_scanC<<<gs, 256>>>(A_log, Dv, Nn);
    k_out<<<nb, 256, smemG>>>(out_w, (float*)d_out, Nn);
}